// round 1
// baseline (speedup 1.0000x reference)
#include <cuda_runtime.h>
#include <math.h>

// ---------------- problem constants ----------------
// B=4096, DG=1024, DI=1024, HG=512, E=8, K=2, H=2048, C=512, TEMP=5
#define NB    4096
#define NDG   1024
#define NDI   1024
#define NHG   512
#define NE    8
#define NH    2048
#define NC    512
#define TEMPR 5.0f
#define NASSIGN (NB*2)

// ---------------- scratch (static device globals; no allocs) ----------------
__device__ float g_hg[NB * NHG];            // gating hidden (relu)        8 MB
__device__ float g_gates[NB * NE];          // dense gates                 128 KB
__device__ int   g_cnt[NE];
__device__ int   g_off[NE];
__device__ int   g_rowlist[NE * NB];        // rows per expert
__device__ float g_gatelist[NE * NB];       // gate per (expert,pos)
__device__ int   g_rowexp[NB * 2];          // per row: its 2 experts
__device__ int   g_rowpos[NB * 2];          // per row: pos within expert list
__device__ float g_He[(size_t)NASSIGN * NH];   // expert hidden, slot-major  64 MB
__device__ float g_P[(size_t)NASSIGN * NC];    // gate-weighted probs        16 MB
__device__ float g_loss;

// ---------------- tiny kernels ----------------
__global__ void zero_counts() {
    if (threadIdx.x < NE) g_cnt[threadIdx.x] = 0;
}

__global__ void offsets_kernel() {
    if (threadIdx.x == 0) {
        int o = 0;
        for (int e = 0; e < NE; e++) { g_off[e] = o; o += g_cnt[e]; }
    }
}

// ---------------- generic tiled fp32 GEMM ----------------
// MODE 0: g_hg = relu(x @ Wg1 + bg1)            M=4096 N=512  K=1024
// MODE 1: g_He = relu(gather(x2) @ W1[e] + b1)  M=cnt  N=2048 K=1024
// MODE 2: g_P  = g_He @ W2[e] + b2              M=cnt  N=512  K=2048
template<int MODE, int BMp>
__global__ __launch_bounds__(256)
void sgemm(const float* __restrict__ Aall,
           const float* __restrict__ Ball,
           const float* __restrict__ biasAll)
{
    constexpr int BNp = 128, BKp = 16;
    constexpr int TM = BMp / 16;           // thread micro-tile rows (16x16 thread grid)
    const int tid = threadIdx.x;
    const int tx = tid & 15;
    const int ty = tid >> 4;

    const int e = (MODE == 0) ? 0 : blockIdx.z;
    int M, Kd, lda, ldb, ldc;
    const float* A; const float* Bm; const float* bias; float* Cm;
    const int* rowlist = nullptr;

    if (MODE == 0) {
        M = NB; Kd = NDG; lda = NDG; ldb = NHG; ldc = NHG;
        A = Aall; Bm = Ball; bias = biasAll; Cm = g_hg;
    } else if (MODE == 1) {
        M = g_cnt[e]; Kd = NDI; lda = NDI; ldb = NH; ldc = NH;
        A = Aall;
        Bm = Ball + (size_t)e * NDI * NH;
        bias = biasAll + e * NH;
        rowlist = g_rowlist + e * NB;
        Cm = g_He + (size_t)g_off[e] * NH;
    } else {
        M = g_cnt[e]; Kd = NH; lda = NH; ldb = NC; ldc = NC;
        A = g_He + (size_t)g_off[e] * NH;
        Bm = Ball + (size_t)e * NH * NC;
        bias = biasAll + e * NC;
        Cm = g_P + (size_t)g_off[e] * NC;
    }

    const int m0 = blockIdx.y * BMp;
    const int n0 = blockIdx.x * BNp;
    if (m0 >= M) return;

    __shared__ float As[BKp][BMp + 4];
    __shared__ float Bs[BKp][BNp];

    // A-tile load plan: thread loads NA float4s (rows fixed across K loop)
    constexpr int NA = BMp / 64;
    const int kq = (tid & 3) * 4;
    int    am[NA];
    size_t arow[NA];
    bool   av[NA];
#pragma unroll
    for (int p = 0; p < NA; p++) {
        int m = p * 64 + (tid >> 2);
        am[p] = m;
        int gm = m0 + m;
        bool v = (gm < M);
        int r;
        if (MODE == 1) r = v ? rowlist[gm] : 0;
        else           r = v ? gm : 0;
        arow[p] = (size_t)r * (size_t)lda;
        av[p] = v;
    }
    // B-tile load plan: 2 float4s per thread
    const int bk0 = tid >> 5;
    const int bnq = (tid & 31) * 4;

    float acc[TM][8];
#pragma unroll
    for (int i = 0; i < TM; i++)
#pragma unroll
        for (int j = 0; j < 8; j++) acc[i][j] = 0.0f;

    for (int k0 = 0; k0 < Kd; k0 += BKp) {
#pragma unroll
        for (int p = 0; p < NA; p++) {
            float4 v = av[p] ? *(const float4*)(A + arow[p] + k0 + kq)
                             : make_float4(0.f, 0.f, 0.f, 0.f);
            As[kq + 0][am[p]] = v.x;
            As[kq + 1][am[p]] = v.y;
            As[kq + 2][am[p]] = v.z;
            As[kq + 3][am[p]] = v.w;
        }
#pragma unroll
        for (int p = 0; p < 2; p++) {
            int k = p * 8 + bk0;
            float4 v = *(const float4*)(Bm + (size_t)(k0 + k) * ldb + n0 + bnq);
            *(float4*)&Bs[k][bnq] = v;
        }
        __syncthreads();

#pragma unroll
        for (int kk = 0; kk < BKp; kk++) {
            float a[TM], b[8];
#pragma unroll
            for (int i = 0; i < TM; i += 4)
                *(float4*)&a[i] = *(const float4*)&As[kk][ty * TM + i];
            *(float4*)&b[0] = *(const float4*)&Bs[kk][tx * 8];
            *(float4*)&b[4] = *(const float4*)&Bs[kk][tx * 8 + 4];
#pragma unroll
            for (int i = 0; i < TM; i++)
#pragma unroll
                for (int j = 0; j < 8; j++)
                    acc[i][j] = fmaf(a[i], b[j], acc[i][j]);
        }
        __syncthreads();
    }

    // epilogue: +bias (+relu for modes 0,1)
    float bj[8];
#pragma unroll
    for (int j = 0; j < 8; j++) bj[j] = bias[n0 + tx * 8 + j];

#pragma unroll
    for (int i = 0; i < TM; i++) {
        int gm = m0 + ty * TM + i;
        if (gm >= M) continue;
        float v[8];
#pragma unroll
        for (int j = 0; j < 8; j++) {
            float t = acc[i][j] + bj[j];
            if (MODE != 2) t = fmaxf(t, 0.0f);
            v[j] = t;
        }
        float* crow = Cm + (size_t)gm * ldc + n0 + tx * 8;
        *(float4*)&crow[0] = *(float4*)&v[0];
        *(float4*)&crow[4] = *(float4*)&v[4];
    }
}

// ---------------- gating layer 2 + top-2 + dispatch ----------------
__global__ __launch_bounds__(256)
void gating_topk(const float* __restrict__ Wg2, const float* __restrict__ bg2)
{
    __shared__ float sW[NE][NHG];   // transposed Wg2 (16 KB)
    __shared__ float sb[NE];
    const int tid = threadIdx.x;
    for (int i = tid; i < NE * NHG; i += 256) {
        int j = i >> 9;        // expert
        int h = i & (NHG - 1); // hidden idx
        sW[j][h] = Wg2[h * NE + j];
    }
    if (tid < NE) sb[tid] = bg2[tid];
    __syncthreads();

    const int warp = tid >> 5, lane = tid & 31;
    const int row = blockIdx.x * 8 + warp;

    float acc[NE];
#pragma unroll
    for (int j = 0; j < NE; j++) acc[j] = 0.0f;

    const float* hr = &g_hg[(size_t)row * NHG];
#pragma unroll 4
    for (int t = 0; t < NHG / 32; t++) {
        float v = hr[t * 32 + lane];
#pragma unroll
        for (int j = 0; j < NE; j++) acc[j] = fmaf(v, sW[j][t * 32 + lane], acc[j]);
    }
#pragma unroll
    for (int j = 0; j < NE; j++)
#pragma unroll
        for (int o = 16; o > 0; o >>= 1)
            acc[j] += __shfl_xor_sync(0xffffffffu, acc[j], o);

    if (lane == 0) {
        float lg[NE];
#pragma unroll
        for (int j = 0; j < NE; j++) lg[j] = acc[j] + sb[j];

        int b0 = 0; float v0 = lg[0];
#pragma unroll
        for (int j = 1; j < NE; j++) if (lg[j] > v0) { v0 = lg[j]; b0 = j; }
        int b1 = -1; float v1 = -INFINITY;
#pragma unroll
        for (int j = 0; j < NE; j++) if (j != b0 && lg[j] > v1) { v1 = lg[j]; b1 = j; }

        float e1 = expf((v1 - v0) / TEMPR);
        float s = 1.0f + e1;
        float gg0 = 1.0f / s, gg1 = e1 / s;

#pragma unroll
        for (int j = 0; j < NE; j++) g_gates[row * NE + j] = 0.0f;
        g_gates[row * NE + b0] = gg0;
        g_gates[row * NE + b1] = gg1;

        int p0 = atomicAdd(&g_cnt[b0], 1);
        g_rowlist[b0 * NB + p0] = row;
        g_gatelist[b0 * NB + p0] = gg0;
        g_rowexp[row * 2 + 0] = b0;
        g_rowpos[row * 2 + 0] = p0;

        int p1 = atomicAdd(&g_cnt[b1], 1);
        g_rowlist[b1 * NB + p1] = row;
        g_gatelist[b1 * NB + p1] = gg1;
        g_rowexp[row * 2 + 1] = b1;
        g_rowpos[row * 2 + 1] = p1;
    }
}

// ---------------- row softmax * gate (in place on g_P) ----------------
__global__ __launch_bounds__(256)
void softmax_gate()
{
    const int e = blockIdx.x;
    const int warp = threadIdx.x >> 5, lane = threadIdx.x & 31;
    const int i = blockIdx.y * 8 + warp;
    if (i >= g_cnt[e]) return;
    const int slot = g_off[e] + i;
    float* P = &g_P[(size_t)slot * NC];

    float v[NC / 32];
    float mx = -INFINITY;
#pragma unroll
    for (int t = 0; t < NC / 32; t++) { v[t] = P[t * 32 + lane]; mx = fmaxf(mx, v[t]); }
#pragma unroll
    for (int o = 16; o > 0; o >>= 1) mx = fmaxf(mx, __shfl_xor_sync(0xffffffffu, mx, o));

    float sum = 0.0f;
#pragma unroll
    for (int t = 0; t < NC / 32; t++) { v[t] = expf(v[t] - mx); sum += v[t]; }
#pragma unroll
    for (int o = 16; o > 0; o >>= 1) sum += __shfl_xor_sync(0xffffffffu, sum, o);

    const float g = g_gatelist[e * NB + i];
    const float inv = g / sum;
#pragma unroll
    for (int t = 0; t < NC / 32; t++) P[t * 32 + lane] = v[t] * inv;
}

// ---------------- load-balance loss ----------------
__global__ __launch_bounds__(256)
void loss_kernel()
{
    const int e = threadIdx.x >> 5, lane = threadIdx.x & 31;
    float s = 0.0f;
    for (int r = lane; r < NB; r += 32) s += g_gates[r * NE + e];
#pragma unroll
    for (int o = 16; o > 0; o >>= 1) s += __shfl_xor_sync(0xffffffffu, s, o);

    __shared__ float imp[NE];
    if (lane == 0) imp[e] = s;
    __syncthreads();

    if (threadIdx.x == 0) {
        double mi = 0.0, ml = 0.0;
        for (int j = 0; j < NE; j++) { mi += (double)imp[j]; ml += (double)g_cnt[j]; }
        mi /= NE; ml /= NE;
        double vi = 0.0, vl = 0.0;
        for (int j = 0; j < NE; j++) {
            double di = (double)imp[j] - mi;  vi += di * di;
            double dl = (double)g_cnt[j] - ml; vl += dl * dl;
        }
        vi /= (NE - 1); vl /= (NE - 1);
        double loss = (vi / (mi * mi + 1e-10) + vl / (ml * ml + 1e-10)) * 0.01;
        g_loss = (float)loss;
    }
}

// ---------------- combine + log ----------------
__global__ __launch_bounds__(256)
void finalize_kernel(float* __restrict__ out, int out_size)
{
    const int row = blockIdx.x;
    const int e0 = g_rowexp[row * 2 + 0];
    const int e1 = g_rowexp[row * 2 + 1];
    const int s0 = g_off[e0] + g_rowpos[row * 2 + 0];
    const int s1 = g_off[e1] + g_rowpos[row * 2 + 1];
    const float* P0 = &g_P[(size_t)s0 * NC];
    const float* P1 = &g_P[(size_t)s1 * NC];
    for (int c = threadIdx.x; c < NC; c += 256) {
        float comb = P0[c] + P1[c];
        if (comb == 0.0f) comb = 2.2204460492503131e-16f;
        out[(size_t)row * NC + c] = logf(comb);
    }
    if (row == 0 && threadIdx.x == 0 && out_size > NB * NC)
        out[NB * NC] = g_loss;
}

// ---------------- launch ----------------
extern "C" void kernel_launch(void* const* d_in, const int* in_sizes, int n_in,
                              void* d_out, int out_size)
{
    const float* x   = (const float*)d_in[0];
    const float* x2  = (const float*)d_in[1];
    const float* Wg1 = (const float*)d_in[2];
    const float* bg1 = (const float*)d_in[3];
    const float* Wg2 = (const float*)d_in[4];
    const float* bg2 = (const float*)d_in[5];
    const float* W1  = (const float*)d_in[6];
    const float* b1  = (const float*)d_in[7];
    const float* W2  = (const float*)d_in[8];
    const float* b2  = (const float*)d_in[9];
    float* out = (float*)d_out;

    zero_counts<<<1, 32>>>();
    // gating GEMM1: hg = relu(x @ Wg1 + bg1)   [4096,512]
    sgemm<0, 64><<<dim3(NHG / 128, NB / 64, 1), 256>>>(x, Wg1, bg1);
    // gating layer2 + top-2 + dispatch lists
    gating_topk<<<NB / 8, 256>>>(Wg2, bg2);
    offsets_kernel<<<1, 32>>>();
    // expert GEMM1: He = relu(gather(x2) @ W1[e] + b1[e])   [cnt_e, 2048]
    sgemm<1, 128><<<dim3(NH / 128, NB / 128, NE), 256>>>(x2, W1, b1);
    // expert GEMM2: O = He @ W2[e] + b2[e]                  [cnt_e, 512]
    sgemm<2, 64><<<dim3(NC / 128, NB / 64, NE), 256>>>(nullptr, W2, b2);
    // softmax * gate
    softmax_gate<<<dim3(NE, NB / 8), 256>>>();
    loss_kernel<<<1, 256>>>();
    finalize_kernel<<<NB, 256>>>(out, out_size);
}

// round 2
// speedup vs baseline: 2.7335x; 2.7335x over previous
#include <cuda_runtime.h>
#include <math.h>
#include <stdint.h>

// ---------------- problem constants ----------------
// B=4096, DG=1024, DI=1024, HG=512, E=8, K=2, H=2048, C=512, TEMP=5
#define NB    4096
#define NDG   1024
#define NDI   1024
#define NHG   512
#define NE    8
#define NH    2048
#define NC    512
#define TEMPR 5.0f
#define NASSIGN (NB*2)

// ---------------- scratch (static device globals; no allocs) ----------------
__device__ float g_hg[NB * NHG];            // gating hidden (relu)
__device__ float g_gates[NB * NE];          // dense gates
__device__ int   g_cnt[NE];
__device__ int   g_off[NE];
__device__ int   g_rowlist[NE * NB];        // rows per expert
__device__ float g_gatelist[NE * NB];       // gate per (expert,pos)
__device__ int   g_rowexp[NB * 2];          // per row: its 2 experts
__device__ int   g_rowpos[NB * 2];          // per row: pos within expert list
__device__ float g_He[(size_t)NASSIGN * NH];   // expert hidden, slot-major
__device__ float g_P[(size_t)NASSIGN * NC];    // gate-weighted probs
__device__ float g_loss;

// ---------------- tiny kernels ----------------
__global__ void zero_counts() {
    if (threadIdx.x < NE) g_cnt[threadIdx.x] = 0;
}

__global__ void offsets_kernel() {
    if (threadIdx.x == 0) {
        int o = 0;
        for (int e = 0; e < NE; e++) { g_off[e] = o; o += g_cnt[e]; }
    }
}

// ---------------- fp32 SIMT GEMM (gating layer 1 only) ----------------
__global__ __launch_bounds__(256)
void sgemm0(const float* __restrict__ A,
            const float* __restrict__ Bm,
            const float* __restrict__ bias)
{
    constexpr int BMp = 64, BNp = 128, BKp = 16, TM = 4;
    const int tid = threadIdx.x;
    const int tx = tid & 15;
    const int ty = tid >> 4;
    const int M = NB, Kd = NDG, lda = NDG, ldb = NHG, ldc = NHG;
    float* Cm = g_hg;

    const int m0 = blockIdx.y * BMp;
    const int n0 = blockIdx.x * BNp;

    __shared__ float As[BKp][BMp + 4];
    __shared__ float Bs[BKp][BNp];

    const int kq = (tid & 3) * 4;
    const int am = tid >> 2;
    const size_t arow = (size_t)(m0 + am) * lda;
    const int bk0 = tid >> 5;
    const int bnq = (tid & 31) * 4;

    float acc[TM][8];
#pragma unroll
    for (int i = 0; i < TM; i++)
#pragma unroll
        for (int j = 0; j < 8; j++) acc[i][j] = 0.0f;

    for (int k0 = 0; k0 < Kd; k0 += BKp) {
        float4 v = *(const float4*)(A + arow + k0 + kq);
        As[kq + 0][am] = v.x;
        As[kq + 1][am] = v.y;
        As[kq + 2][am] = v.z;
        As[kq + 3][am] = v.w;
#pragma unroll
        for (int p = 0; p < 2; p++) {
            int k = p * 8 + bk0;
            *(float4*)&Bs[k][bnq] = *(const float4*)(Bm + (size_t)(k0 + k) * ldb + n0 + bnq);
        }
        __syncthreads();
#pragma unroll
        for (int kk = 0; kk < BKp; kk++) {
            float a[TM], b[8];
            *(float4*)&a[0] = *(const float4*)&As[kk][ty * TM];
            *(float4*)&b[0] = *(const float4*)&Bs[kk][tx * 8];
            *(float4*)&b[4] = *(const float4*)&Bs[kk][tx * 8 + 4];
#pragma unroll
            for (int i = 0; i < TM; i++)
#pragma unroll
                for (int j = 0; j < 8; j++)
                    acc[i][j] = fmaf(a[i], b[j], acc[i][j]);
        }
        __syncthreads();
    }

    float bj[8];
#pragma unroll
    for (int j = 0; j < 8; j++) bj[j] = bias[n0 + tx * 8 + j];
#pragma unroll
    for (int i = 0; i < TM; i++) {
        int gm = m0 + ty * TM + i;
        float v[8];
#pragma unroll
        for (int j = 0; j < 8; j++) v[j] = fmaxf(acc[i][j] + bj[j], 0.0f);
        float* crow = Cm + (size_t)gm * ldc + n0 + tx * 8;
        *(float4*)&crow[0] = *(float4*)&v[0];
        *(float4*)&crow[4] = *(float4*)&v[4];
    }
}

// ---------------- tf32 tensor-core GEMM for expert layers ----------------
__device__ __forceinline__ float tf32r(float x) {
    uint32_t u;
    asm("cvt.rna.tf32.f32 %0, %1;" : "=r"(u) : "f"(x));
    return __uint_as_float(u);
}

__device__ __forceinline__ void mma_tf32(float* d, const uint32_t* a,
                                         const uint32_t* b, const float* c) {
    asm volatile(
        "mma.sync.aligned.m16n8k8.row.col.f32.tf32.tf32.f32 "
        "{%0,%1,%2,%3}, {%4,%5,%6,%7}, {%8,%9}, {%10,%11,%12,%13};\n"
        : "=f"(d[0]), "=f"(d[1]), "=f"(d[2]), "=f"(d[3])
        : "r"(a[0]), "r"(a[1]), "r"(a[2]), "r"(a[3]),
          "r"(b[0]), "r"(b[1]),
          "f"(c[0]), "f"(c[1]), "f"(c[2]), "f"(c[3]));
}

// MODE 1: g_He = relu(gather(x2) @ W1[e] + b1[e])  M=cnt_e N=2048 K=1024
// MODE 2: g_P  = g_He @ W2[e] + b2[e]              M=cnt_e N=512  K=2048
template<int MODE>
__global__ __launch_bounds__(256, 2)
void tmma(const float* __restrict__ Aall,
          const float* __restrict__ Wall,
          const float* __restrict__ biasAll)
{
    constexpr int BM = 128, BN = 128, BK = 16;
    constexpr int LDA = 20, LDB = 136;

    const int e = blockIdx.z;
    const int M = g_cnt[e];
    const int m0 = blockIdx.y * BM;
    if (m0 >= M) return;
    const int n0 = blockIdx.x * BN;

    int Kd, ldw, ldc, ldaG;
    const float* A; const float* W; const float* bias; float* C;
    const int* rowlist = nullptr;
    if (MODE == 1) {
        Kd = NDI; ldw = NH; ldc = NH; ldaG = NDI;
        A = Aall; W = Wall + (size_t)e * NDI * NH; bias = biasAll + e * NH;
        rowlist = g_rowlist + e * NB;
        C = g_He + (size_t)g_off[e] * NH;
    } else {
        Kd = NH; ldw = NC; ldc = NC; ldaG = NH;
        A = g_He + (size_t)g_off[e] * NH;
        W = Wall + (size_t)e * NH * NC; bias = biasAll + e * NC;
        C = g_P + (size_t)g_off[e] * NC;
    }

    __shared__ float As[2][BM][LDA];
    __shared__ float Bs[2][BK][LDB];

    const int tid = threadIdx.x;
    // A gmem plan: 2 float4 per thread: rows tid/4 + {0,64}, cols (tid%4)*4
    const int arow0 = tid >> 2;
    const int acol  = (tid & 3) * 4;
    size_t aoff[2];
#pragma unroll
    for (int p = 0; p < 2; p++) {
        int gm = m0 + arow0 + p * 64;
        int r;
        if (MODE == 1) r = (gm < M) ? rowlist[gm] : rowlist[0];
        else           r = (gm < M) ? gm : 0;
        aoff[p] = (size_t)r * (size_t)ldaG;
    }
    // B gmem plan: 2 float4 per thread: rows tid/32 + {0,8}, cols (tid%32)*4
    const int brow0 = tid >> 5;
    const int bcol  = (tid & 31) * 4;

    const int warp = tid >> 5;
    const int wm = warp >> 1;         // 0..3  (M)
    const int wn = warp & 1;          // 0..1  (N)
    const int lane = tid & 31;
    const int g  = lane >> 2;         // group 0..7
    const int tg = lane & 3;          // 0..3

    float acc[2][8][4];
#pragma unroll
    for (int i = 0; i < 2; i++)
#pragma unroll
        for (int j = 0; j < 8; j++)
#pragma unroll
            for (int q = 0; q < 4; q++) acc[i][j][q] = 0.0f;

    float4 ra[2], rb[2];
    auto loadG = [&](int k0) {
#pragma unroll
        for (int p = 0; p < 2; p++)
            ra[p] = *(const float4*)(A + aoff[p] + k0 + acol);
#pragma unroll
        for (int p = 0; p < 2; p++)
            rb[p] = *(const float4*)(W + (size_t)(k0 + brow0 + p * 8) * ldw + n0 + bcol);
    };
    auto storeS = [&](int s) {
#pragma unroll
        for (int p = 0; p < 2; p++) {
            float* d = &As[s][arow0 + p * 64][acol];
            d[0] = tf32r(ra[p].x); d[1] = tf32r(ra[p].y);
            d[2] = tf32r(ra[p].z); d[3] = tf32r(ra[p].w);
        }
#pragma unroll
        for (int p = 0; p < 2; p++) {
            float* d = &Bs[s][brow0 + p * 8][bcol];
            d[0] = tf32r(rb[p].x); d[1] = tf32r(rb[p].y);
            d[2] = tf32r(rb[p].z); d[3] = tf32r(rb[p].w);
        }
    };

    loadG(0);
    storeS(0);
    __syncthreads();

    const int T = Kd / BK;
    for (int t = 0; t < T; t++) {
        const int s = t & 1;
        if (t + 1 < T) loadG((t + 1) * BK);

#pragma unroll
        for (int k8 = 0; k8 < BK; k8 += 8) {
            uint32_t af[2][4];
#pragma unroll
            for (int mt = 0; mt < 2; mt++) {
                const int mr = wm * 32 + mt * 16;
                af[mt][0] = __float_as_uint(As[s][mr + g    ][k8 + tg]);
                af[mt][1] = __float_as_uint(As[s][mr + g + 8][k8 + tg]);
                af[mt][2] = __float_as_uint(As[s][mr + g    ][k8 + tg + 4]);
                af[mt][3] = __float_as_uint(As[s][mr + g + 8][k8 + tg + 4]);
            }
            uint32_t bf[8][2];
#pragma unroll
            for (int nt = 0; nt < 8; nt++) {
                const int nc = wn * 64 + nt * 8 + g;
                bf[nt][0] = __float_as_uint(Bs[s][k8 + tg    ][nc]);
                bf[nt][1] = __float_as_uint(Bs[s][k8 + tg + 4][nc]);
            }
#pragma unroll
            for (int mt = 0; mt < 2; mt++)
#pragma unroll
                for (int nt = 0; nt < 8; nt++)
                    mma_tf32(acc[mt][nt], af[mt], bf[nt], acc[mt][nt]);
        }

        if (t + 1 < T) {
            storeS((t + 1) & 1);
            __syncthreads();
        }
    }

    // epilogue: +bias (+relu for MODE 1)
#pragma unroll
    for (int mt = 0; mt < 2; mt++) {
        const int gm1 = m0 + wm * 32 + mt * 16 + g;
        const int gm2 = gm1 + 8;
#pragma unroll
        for (int nt = 0; nt < 8; nt++) {
            const int col = n0 + wn * 64 + nt * 8 + tg * 2;
            const float b0 = bias[col], b1 = bias[col + 1];
            if (gm1 < M) {
                float v0 = acc[mt][nt][0] + b0;
                float v1 = acc[mt][nt][1] + b1;
                if (MODE == 1) { v0 = fmaxf(v0, 0.f); v1 = fmaxf(v1, 0.f); }
                *(float2*)(C + (size_t)gm1 * ldc + col) = make_float2(v0, v1);
            }
            if (gm2 < M) {
                float v0 = acc[mt][nt][2] + b0;
                float v1 = acc[mt][nt][3] + b1;
                if (MODE == 1) { v0 = fmaxf(v0, 0.f); v1 = fmaxf(v1, 0.f); }
                *(float2*)(C + (size_t)gm2 * ldc + col) = make_float2(v0, v1);
            }
        }
    }
}

// ---------------- gating layer 2 + top-2 + dispatch ----------------
__global__ __launch_bounds__(256)
void gating_topk(const float* __restrict__ Wg2, const float* __restrict__ bg2)
{
    __shared__ float sW[NE][NHG];
    __shared__ float sb[NE];
    const int tid = threadIdx.x;
    for (int i = tid; i < NE * NHG; i += 256) {
        int j = i >> 9;
        int h = i & (NHG - 1);
        sW[j][h] = Wg2[h * NE + j];
    }
    if (tid < NE) sb[tid] = bg2[tid];
    __syncthreads();

    const int warp = tid >> 5, lane = tid & 31;
    const int row = blockIdx.x * 8 + warp;

    float acc[NE];
#pragma unroll
    for (int j = 0; j < NE; j++) acc[j] = 0.0f;

    const float* hr = &g_hg[(size_t)row * NHG];
#pragma unroll 4
    for (int t = 0; t < NHG / 32; t++) {
        float v = hr[t * 32 + lane];
#pragma unroll
        for (int j = 0; j < NE; j++) acc[j] = fmaf(v, sW[j][t * 32 + lane], acc[j]);
    }
#pragma unroll
    for (int j = 0; j < NE; j++)
#pragma unroll
        for (int o = 16; o > 0; o >>= 1)
            acc[j] += __shfl_xor_sync(0xffffffffu, acc[j], o);

    if (lane == 0) {
        float lg[NE];
#pragma unroll
        for (int j = 0; j < NE; j++) lg[j] = acc[j] + sb[j];

        int b0 = 0; float v0 = lg[0];
#pragma unroll
        for (int j = 1; j < NE; j++) if (lg[j] > v0) { v0 = lg[j]; b0 = j; }
        int b1 = -1; float v1 = -INFINITY;
#pragma unroll
        for (int j = 0; j < NE; j++) if (j != b0 && lg[j] > v1) { v1 = lg[j]; b1 = j; }

        float e1 = expf((v1 - v0) / TEMPR);
        float s = 1.0f + e1;
        float gg0 = 1.0f / s, gg1 = e1 / s;

#pragma unroll
        for (int j = 0; j < NE; j++) g_gates[row * NE + j] = 0.0f;
        g_gates[row * NE + b0] = gg0;
        g_gates[row * NE + b1] = gg1;

        int p0 = atomicAdd(&g_cnt[b0], 1);
        g_rowlist[b0 * NB + p0] = row;
        g_gatelist[b0 * NB + p0] = gg0;
        g_rowexp[row * 2 + 0] = b0;
        g_rowpos[row * 2 + 0] = p0;

        int p1 = atomicAdd(&g_cnt[b1], 1);
        g_rowlist[b1 * NB + p1] = row;
        g_gatelist[b1 * NB + p1] = gg1;
        g_rowexp[row * 2 + 1] = b1;
        g_rowpos[row * 2 + 1] = p1;
    }
}

// ---------------- row softmax * gate (in place on g_P) ----------------
__global__ __launch_bounds__(256)
void softmax_gate()
{
    const int e = blockIdx.x;
    const int warp = threadIdx.x >> 5, lane = threadIdx.x & 31;
    const int i = blockIdx.y * 8 + warp;
    if (i >= g_cnt[e]) return;
    const int slot = g_off[e] + i;
    float* P = &g_P[(size_t)slot * NC];

    float v[NC / 32];
    float mx = -INFINITY;
#pragma unroll
    for (int t = 0; t < NC / 32; t++) { v[t] = P[t * 32 + lane]; mx = fmaxf(mx, v[t]); }
#pragma unroll
    for (int o = 16; o > 0; o >>= 1) mx = fmaxf(mx, __shfl_xor_sync(0xffffffffu, mx, o));

    float sum = 0.0f;
#pragma unroll
    for (int t = 0; t < NC / 32; t++) { v[t] = expf(v[t] - mx); sum += v[t]; }
#pragma unroll
    for (int o = 16; o > 0; o >>= 1) sum += __shfl_xor_sync(0xffffffffu, sum, o);

    const float gt = g_gatelist[e * NB + i];
    const float inv = gt / sum;
#pragma unroll
    for (int t = 0; t < NC / 32; t++) P[t * 32 + lane] = v[t] * inv;
}

// ---------------- load-balance loss ----------------
__global__ __launch_bounds__(256)
void loss_kernel()
{
    const int e = threadIdx.x >> 5, lane = threadIdx.x & 31;
    float s = 0.0f;
    for (int r = lane; r < NB; r += 32) s += g_gates[r * NE + e];
#pragma unroll
    for (int o = 16; o > 0; o >>= 1) s += __shfl_xor_sync(0xffffffffu, s, o);

    __shared__ float imp[NE];
    if (lane == 0) imp[e] = s;
    __syncthreads();

    if (threadIdx.x == 0) {
        double mi = 0.0, ml = 0.0;
        for (int j = 0; j < NE; j++) { mi += (double)imp[j]; ml += (double)g_cnt[j]; }
        mi /= NE; ml /= NE;
        double vi = 0.0, vl = 0.0;
        for (int j = 0; j < NE; j++) {
            double di = (double)imp[j] - mi;  vi += di * di;
            double dl = (double)g_cnt[j] - ml; vl += dl * dl;
        }
        vi /= (NE - 1); vl /= (NE - 1);
        double loss = (vi / (mi * mi + 1e-10) + vl / (ml * ml + 1e-10)) * 0.01;
        g_loss = (float)loss;
    }
}

// ---------------- combine + log ----------------
__global__ __launch_bounds__(256)
void finalize_kernel(float* __restrict__ out, int out_size)
{
    const int row = blockIdx.x;
    const int e0 = g_rowexp[row * 2 + 0];
    const int e1 = g_rowexp[row * 2 + 1];
    const int s0 = g_off[e0] + g_rowpos[row * 2 + 0];
    const int s1 = g_off[e1] + g_rowpos[row * 2 + 1];
    const float* P0 = &g_P[(size_t)s0 * NC];
    const float* P1 = &g_P[(size_t)s1 * NC];
    for (int c = threadIdx.x; c < NC; c += 256) {
        float comb = P0[c] + P1[c];
        if (comb == 0.0f) comb = 2.2204460492503131e-16f;
        out[(size_t)row * NC + c] = logf(comb);
    }
    if (row == 0 && threadIdx.x == 0 && out_size > NB * NC)
        out[NB * NC] = g_loss;
}

// ---------------- launch ----------------
extern "C" void kernel_launch(void* const* d_in, const int* in_sizes, int n_in,
                              void* d_out, int out_size)
{
    const float* x   = (const float*)d_in[0];
    const float* x2  = (const float*)d_in[1];
    const float* Wg1 = (const float*)d_in[2];
    const float* bg1 = (const float*)d_in[3];
    const float* Wg2 = (const float*)d_in[4];
    const float* bg2 = (const float*)d_in[5];
    const float* W1  = (const float*)d_in[6];
    const float* b1  = (const float*)d_in[7];
    const float* W2  = (const float*)d_in[8];
    const float* b2  = (const float*)d_in[9];
    float* out = (float*)d_out;

    zero_counts<<<1, 32>>>();
    // gating GEMM1 (fp32 SIMT, precision-critical for top-2): hg = relu(x @ Wg1 + bg1)
    sgemm0<<<dim3(NHG / 128, NB / 64, 1), 256>>>(x, Wg1, bg1);
    // gating layer2 + top-2 + dispatch lists
    gating_topk<<<NB / 8, 256>>>(Wg2, bg2);
    offsets_kernel<<<1, 32>>>();
    // expert GEMM1 (tf32 tensor): He = relu(gather(x2) @ W1[e] + b1[e])
    tmma<1><<<dim3(NH / 128, NB / 128, NE), 256>>>(x2, W1, b1);
    // expert GEMM2 (tf32 tensor): O = He @ W2[e] + b2[e]
    tmma<2><<<dim3(NC / 128, NB / 128, NE), 256>>>(nullptr, W2, b2);
    // softmax * gate
    softmax_gate<<<dim3(NE, NB / 8), 256>>>();
    loss_kernel<<<1, 256>>>();
    finalize_kernel<<<NB, 256>>>(out, out_size);
}

// round 3
// speedup vs baseline: 4.5542x; 1.6661x over previous
#include <cuda_runtime.h>
#include <cuda_bf16.h>
#include <math.h>
#include <stdint.h>

// ---------------- problem constants ----------------
#define NB    4096
#define NDG   1024
#define NDI   1024
#define NHG   512
#define NE    8
#define NH    2048
#define NC    512
#define TEMPR 5.0f
#define NASSIGN (NB*2)

// ---------------- scratch ----------------
__device__ float g_hg[NB * NHG];
__device__ float g_gates[NB * NE];
__device__ int   g_cnt[NE];
__device__ int   g_off[NE];
__device__ int   g_rowlist[NE * NB];
__device__ float g_gatelist[NE * NB];
__device__ int   g_rowexp[NB * 2];
__device__ int   g_rowpos[NB * 2];
__device__ __nv_bfloat16 g_He[(size_t)NASSIGN * NH];
__device__ float g_P[(size_t)NASSIGN * NC];
__device__ float g_loss;

__global__ void zero_counts() {
    if (threadIdx.x < NE) g_cnt[threadIdx.x] = 0;
}
__global__ void offsets_kernel() {
    if (threadIdx.x == 0) {
        int o = 0;
        for (int e = 0; e < NE; e++) { g_off[e] = o; o += g_cnt[e]; }
    }
}

// ---------------- helpers ----------------
__device__ __forceinline__ uint32_t packbf(float a, float b) {
    __nv_bfloat162 h = __floats2bfloat162_rn(a, b);
    return *reinterpret_cast<uint32_t*>(&h);
}

__device__ __forceinline__ void mma_bf16(float* d, const uint32_t* a,
                                         const uint32_t* b, const float* c) {
    asm volatile(
        "mma.sync.aligned.m16n8k16.row.col.f32.bf16.bf16.f32 "
        "{%0,%1,%2,%3}, {%4,%5,%6,%7}, {%8,%9}, {%10,%11,%12,%13};\n"
        : "=f"(d[0]), "=f"(d[1]), "=f"(d[2]), "=f"(d[3])
        : "r"(a[0]), "r"(a[1]), "r"(a[2]), "r"(a[3]),
          "r"(b[0]), "r"(b[1]),
          "f"(c[0]), "f"(c[1]), "f"(c[2]), "f"(c[3]));
}

// ============================================================================
// Expert GEMMs, bf16 tensor cores.
// MODE 1: He = relu(gather(x2) @ W1[e] + b1[e])   M=cnt_e N=2048 K=1024
// MODE 2: P  = He @ W2[e] + b2[e]                 M=cnt_e N=512  K=2048
// SMEM: A as b32 k-pairs [m][kp] pad 20; B as b32 k-pair-interleaved [kp][n] pad 136.
// ============================================================================
template<int MODE>
__global__ __launch_bounds__(256, 2)
void emma(const float* __restrict__ Af,
          const float* __restrict__ Wall,
          const float* __restrict__ biasAll)
{
    constexpr int BM = 128, BK = 32;
    constexpr int LDA = 20, LDB = 136;

    const int e = blockIdx.z;
    const int M = g_cnt[e];
    const int m0 = blockIdx.y * BM;
    if (m0 >= M) return;
    const int n0 = blockIdx.x * 128;

    constexpr int Kd  = (MODE == 1) ? NDI : NH;
    constexpr int ldw = (MODE == 1) ? NH  : NC;
    const float* W    = Wall + (size_t)e * Kd * ldw;
    const float* bias = biasAll + e * ldw;
    const int* rowlist = g_rowlist + e * NB;
    const size_t offE = (size_t)g_off[e];
    const __nv_bfloat16* Ab = g_He + offE * NH;   // MODE 2 input

    __shared__ uint32_t As[2][BM][LDA];
    __shared__ uint32_t Bs[2][16][LDB];

    const int tid = threadIdx.x;
    // A gmem plan: 2 chunks of 8 k-values
    int arow[2], akc[2];
    size_t aoff[2];
#pragma unroll
    for (int c = 0; c < 2; c++) {
        int q = tid + 256 * c;
        arow[c] = q >> 2;
        akc[c]  = (q & 3) * 8;
        int gm = m0 + arow[c];
        if (MODE == 1) {
            int r = (gm < M) ? rowlist[gm] : rowlist[0];
            aoff[c] = (size_t)r * NDI;
        } else {
            int r = (gm < M) ? gm : 0;
            aoff[c] = (size_t)r * NH;
        }
    }
    // B gmem plan: 2 chunks of (2 k rows x 4 n)
    int bkp[2], bnq[2];
#pragma unroll
    for (int c = 0; c < 2; c++) {
        int q = tid + 256 * c;
        bkp[c] = q >> 5;
        bnq[c] = (q & 31) * 4;
    }

    const int warp = tid >> 5;
    const int wm = warp >> 1, wn = warp & 1;
    const int lane = tid & 31;
    const int g = lane >> 2, tg = lane & 3;

    float acc[2][8][4];
#pragma unroll
    for (int i = 0; i < 2; i++)
#pragma unroll
        for (int j = 0; j < 8; j++)
#pragma unroll
            for (int q = 0; q < 4; q++) acc[i][j][q] = 0.0f;

    float4 ra[2][2];
    uint4  rab[2];
    float4 rb[2][2];

    auto LDGt = [&](int k0) {
#pragma unroll
        for (int c = 0; c < 2; c++) {
            if (MODE == 1) {
                ra[c][0] = *(const float4*)(Af + aoff[c] + k0 + akc[c]);
                ra[c][1] = *(const float4*)(Af + aoff[c] + k0 + akc[c] + 4);
            } else {
                rab[c] = *(const uint4*)(Ab + aoff[c] + k0 + akc[c]);
            }
        }
#pragma unroll
        for (int c = 0; c < 2; c++) {
            rb[c][0] = *(const float4*)(W + (size_t)(k0 + 2 * bkp[c]) * ldw + n0 + bnq[c]);
            rb[c][1] = *(const float4*)(W + (size_t)(k0 + 2 * bkp[c] + 1) * ldw + n0 + bnq[c]);
        }
    };
    auto STSt = [&](int s) {
#pragma unroll
        for (int c = 0; c < 2; c++) {
            if (MODE == 1) {
                uint4 u;
                u.x = packbf(ra[c][0].x, ra[c][0].y);
                u.y = packbf(ra[c][0].z, ra[c][0].w);
                u.z = packbf(ra[c][1].x, ra[c][1].y);
                u.w = packbf(ra[c][1].z, ra[c][1].w);
                *(uint4*)&As[s][arow[c]][akc[c] >> 1] = u;
            } else {
                *(uint4*)&As[s][arow[c]][akc[c] >> 1] = rab[c];
            }
        }
#pragma unroll
        for (int c = 0; c < 2; c++) {
            uint4 u;
            u.x = packbf(rb[c][0].x, rb[c][1].x);
            u.y = packbf(rb[c][0].y, rb[c][1].y);
            u.z = packbf(rb[c][0].z, rb[c][1].z);
            u.w = packbf(rb[c][0].w, rb[c][1].w);
            *(uint4*)&Bs[s][bkp[c]][bnq[c]] = u;
        }
    };

    LDGt(0);
    STSt(0);
    __syncthreads();

    const int T = Kd / BK;
    for (int t = 0; t < T; t++) {
        const int s = t & 1;
        if (t + 1 < T) LDGt((t + 1) * BK);

#pragma unroll
        for (int ksub = 0; ksub < 2; ksub++) {
            const int kb = ksub * 8;
            uint32_t af[2][4];
#pragma unroll
            for (int mt = 0; mt < 2; mt++) {
                const int mr = wm * 32 + mt * 16;
                af[mt][0] = As[s][mr + g    ][kb + tg];
                af[mt][1] = As[s][mr + g + 8][kb + tg];
                af[mt][2] = As[s][mr + g    ][kb + tg + 4];
                af[mt][3] = As[s][mr + g + 8][kb + tg + 4];
            }
#pragma unroll
            for (int nt = 0; nt < 8; nt++) {
                const int nc = wn * 64 + nt * 8 + g;
                uint32_t bf[2];
                bf[0] = Bs[s][kb + tg    ][nc];
                bf[1] = Bs[s][kb + tg + 4][nc];
#pragma unroll
                for (int mt = 0; mt < 2; mt++)
                    mma_bf16(acc[mt][nt], af[mt], bf, acc[mt][nt]);
            }
        }

        if (t + 1 < T) {
            STSt((t + 1) & 1);
            __syncthreads();
        }
    }

    // epilogue
    __nv_bfloat16* Cb = g_He + offE * NH;   // MODE 1 out
    float*         Cf = g_P  + offE * NC;   // MODE 2 out
#pragma unroll
    for (int mt = 0; mt < 2; mt++) {
        const int gm1 = m0 + wm * 32 + mt * 16 + g;
        const int gm2 = gm1 + 8;
#pragma unroll
        for (int nt = 0; nt < 8; nt++) {
            const int col = n0 + wn * 64 + nt * 8 + tg * 2;
            const float b0 = bias[col], b1 = bias[col + 1];
            if (MODE == 1) {
                if (gm1 < M) {
                    float v0 = fmaxf(acc[mt][nt][0] + b0, 0.f);
                    float v1 = fmaxf(acc[mt][nt][1] + b1, 0.f);
                    *reinterpret_cast<__nv_bfloat162*>(Cb + (size_t)gm1 * NH + col) =
                        __floats2bfloat162_rn(v0, v1);
                }
                if (gm2 < M) {
                    float v0 = fmaxf(acc[mt][nt][2] + b0, 0.f);
                    float v1 = fmaxf(acc[mt][nt][3] + b1, 0.f);
                    *reinterpret_cast<__nv_bfloat162*>(Cb + (size_t)gm2 * NH + col) =
                        __floats2bfloat162_rn(v0, v1);
                }
            } else {
                if (gm1 < M)
                    *(float2*)(Cf + (size_t)gm1 * NC + col) =
                        make_float2(acc[mt][nt][0] + b0, acc[mt][nt][1] + b1);
                if (gm2 < M)
                    *(float2*)(Cf + (size_t)gm2 * NC + col) =
                        make_float2(acc[mt][nt][2] + b0, acc[mt][nt][3] + b1);
            }
        }
    }
}

// ============================================================================
// Gating layer 1: compensated bf16-split (hi*hi + hi*lo + lo*hi ~ fp32 acc).
// g_hg = relu(x @ Wg1 + bg1)   M=4096 N=512 K=1024. Single-buffered.
// ============================================================================
__global__ __launch_bounds__(256, 2)
void gemm0_split(const float* __restrict__ A,
                 const float* __restrict__ W,
                 const float* __restrict__ bias)
{
    constexpr int BM = 128, BK = 32;
    constexpr int LDA = 20, LDB = 136;
    constexpr int ldw = NHG;

    const int m0 = blockIdx.y * BM;
    const int n0 = blockIdx.x * 128;

    __shared__ uint32_t AsH[BM][LDA];
    __shared__ uint32_t AsL[BM][LDA];
    __shared__ uint32_t BsH[16][LDB];
    __shared__ uint32_t BsL[16][LDB];

    const int tid = threadIdx.x;
    int arow[2], akc[2];
    size_t aoff[2];
#pragma unroll
    for (int c = 0; c < 2; c++) {
        int q = tid + 256 * c;
        arow[c] = q >> 2;
        akc[c]  = (q & 3) * 8;
        aoff[c] = (size_t)(m0 + arow[c]) * NDG;
    }
    int bkp[2], bnq[2];
#pragma unroll
    for (int c = 0; c < 2; c++) {
        int q = tid + 256 * c;
        bkp[c] = q >> 5;
        bnq[c] = (q & 31) * 4;
    }

    const int warp = tid >> 5;
    const int wm = warp >> 1, wn = warp & 1;
    const int lane = tid & 31;
    const int g = lane >> 2, tg = lane & 3;

    float acc[2][8][4];
#pragma unroll
    for (int i = 0; i < 2; i++)
#pragma unroll
        for (int j = 0; j < 8; j++)
#pragma unroll
            for (int q = 0; q < 4; q++) acc[i][j][q] = 0.0f;

    auto splitpack = [](float a, float b, uint32_t& uh, uint32_t& ul) {
        __nv_bfloat16 ha = __float2bfloat16_rn(a);
        __nv_bfloat16 hb = __float2bfloat16_rn(b);
        float la = a - __bfloat162float(ha);
        float lb = b - __bfloat162float(hb);
        __nv_bfloat162 h2; h2.x = ha; h2.y = hb;
        uh = *reinterpret_cast<uint32_t*>(&h2);
        ul = packbf(la, lb);
    };

    const int T = NDG / BK;
    for (int t = 0; t < T; t++) {
        const int k0 = t * BK;
        float4 ra[2][2], rb[2][2];
#pragma unroll
        for (int c = 0; c < 2; c++) {
            ra[c][0] = *(const float4*)(A + aoff[c] + k0 + akc[c]);
            ra[c][1] = *(const float4*)(A + aoff[c] + k0 + akc[c] + 4);
            rb[c][0] = *(const float4*)(W + (size_t)(k0 + 2 * bkp[c]) * ldw + n0 + bnq[c]);
            rb[c][1] = *(const float4*)(W + (size_t)(k0 + 2 * bkp[c] + 1) * ldw + n0 + bnq[c]);
        }
        __syncthreads();   // previous tile fully consumed
#pragma unroll
        for (int c = 0; c < 2; c++) {
            uint4 uh, ul;
            splitpack(ra[c][0].x, ra[c][0].y, uh.x, ul.x);
            splitpack(ra[c][0].z, ra[c][0].w, uh.y, ul.y);
            splitpack(ra[c][1].x, ra[c][1].y, uh.z, ul.z);
            splitpack(ra[c][1].z, ra[c][1].w, uh.w, ul.w);
            *(uint4*)&AsH[arow[c]][akc[c] >> 1] = uh;
            *(uint4*)&AsL[arow[c]][akc[c] >> 1] = ul;
        }
#pragma unroll
        for (int c = 0; c < 2; c++) {
            uint4 uh, ul;
            splitpack(rb[c][0].x, rb[c][1].x, uh.x, ul.x);
            splitpack(rb[c][0].y, rb[c][1].y, uh.y, ul.y);
            splitpack(rb[c][0].z, rb[c][1].z, uh.z, ul.z);
            splitpack(rb[c][0].w, rb[c][1].w, uh.w, ul.w);
            *(uint4*)&BsH[bkp[c]][bnq[c]] = uh;
            *(uint4*)&BsL[bkp[c]][bnq[c]] = ul;
        }
        __syncthreads();

#pragma unroll
        for (int ksub = 0; ksub < 2; ksub++) {
            const int kb = ksub * 8;
            uint32_t afh[2][4], afl[2][4];
#pragma unroll
            for (int mt = 0; mt < 2; mt++) {
                const int mr = wm * 32 + mt * 16;
                afh[mt][0] = AsH[mr + g    ][kb + tg];
                afh[mt][1] = AsH[mr + g + 8][kb + tg];
                afh[mt][2] = AsH[mr + g    ][kb + tg + 4];
                afh[mt][3] = AsH[mr + g + 8][kb + tg + 4];
                afl[mt][0] = AsL[mr + g    ][kb + tg];
                afl[mt][1] = AsL[mr + g + 8][kb + tg];
                afl[mt][2] = AsL[mr + g    ][kb + tg + 4];
                afl[mt][3] = AsL[mr + g + 8][kb + tg + 4];
            }
#pragma unroll
            for (int nt = 0; nt < 8; nt++) {
                const int nc = wn * 64 + nt * 8 + g;
                uint32_t bfh[2], bfl[2];
                bfh[0] = BsH[kb + tg    ][nc];
                bfh[1] = BsH[kb + tg + 4][nc];
                bfl[0] = BsL[kb + tg    ][nc];
                bfl[1] = BsL[kb + tg + 4][nc];
#pragma unroll
                for (int mt = 0; mt < 2; mt++) {
                    mma_bf16(acc[mt][nt], afh[mt], bfh, acc[mt][nt]);
                    mma_bf16(acc[mt][nt], afh[mt], bfl, acc[mt][nt]);
                    mma_bf16(acc[mt][nt], afl[mt], bfh, acc[mt][nt]);
                }
            }
        }
    }

#pragma unroll
    for (int mt = 0; mt < 2; mt++) {
        const int gm1 = m0 + wm * 32 + mt * 16 + g;
        const int gm2 = gm1 + 8;
#pragma unroll
        for (int nt = 0; nt < 8; nt++) {
            const int col = n0 + wn * 64 + nt * 8 + tg * 2;
            const float b0 = bias[col], b1 = bias[col + 1];
            *(float2*)(g_hg + (size_t)gm1 * NHG + col) =
                make_float2(fmaxf(acc[mt][nt][0] + b0, 0.f), fmaxf(acc[mt][nt][1] + b1, 0.f));
            *(float2*)(g_hg + (size_t)gm2 * NHG + col) =
                make_float2(fmaxf(acc[mt][nt][2] + b0, 0.f), fmaxf(acc[mt][nt][3] + b1, 0.f));
        }
    }
}

// ---------------- gating layer 2 + top-2 + dispatch ----------------
__global__ __launch_bounds__(256)
void gating_topk(const float* __restrict__ Wg2, const float* __restrict__ bg2)
{
    __shared__ float sW[NE][NHG];
    __shared__ float sb[NE];
    const int tid = threadIdx.x;
    for (int i = tid; i < NE * NHG; i += 256) {
        int j = i >> 9;
        int h = i & (NHG - 1);
        sW[j][h] = Wg2[h * NE + j];
    }
    if (tid < NE) sb[tid] = bg2[tid];
    __syncthreads();

    const int warp = tid >> 5, lane = tid & 31;
    const int row = blockIdx.x * 8 + warp;

    float acc[NE];
#pragma unroll
    for (int j = 0; j < NE; j++) acc[j] = 0.0f;

    const float* hr = &g_hg[(size_t)row * NHG];
#pragma unroll 4
    for (int t = 0; t < NHG / 32; t++) {
        float v = hr[t * 32 + lane];
#pragma unroll
        for (int j = 0; j < NE; j++) acc[j] = fmaf(v, sW[j][t * 32 + lane], acc[j]);
    }
#pragma unroll
    for (int j = 0; j < NE; j++)
#pragma unroll
        for (int o = 16; o > 0; o >>= 1)
            acc[j] += __shfl_xor_sync(0xffffffffu, acc[j], o);

    if (lane == 0) {
        float lg[NE];
#pragma unroll
        for (int j = 0; j < NE; j++) lg[j] = acc[j] + sb[j];

        int b0 = 0; float v0 = lg[0];
#pragma unroll
        for (int j = 1; j < NE; j++) if (lg[j] > v0) { v0 = lg[j]; b0 = j; }
        int b1 = -1; float v1 = -INFINITY;
#pragma unroll
        for (int j = 0; j < NE; j++) if (j != b0 && lg[j] > v1) { v1 = lg[j]; b1 = j; }

        float e1 = expf((v1 - v0) / TEMPR);
        float s = 1.0f + e1;
        float gg0 = 1.0f / s, gg1 = e1 / s;

#pragma unroll
        for (int j = 0; j < NE; j++) g_gates[row * NE + j] = 0.0f;
        g_gates[row * NE + b0] = gg0;
        g_gates[row * NE + b1] = gg1;

        int p0 = atomicAdd(&g_cnt[b0], 1);
        g_rowlist[b0 * NB + p0] = row;
        g_gatelist[b0 * NB + p0] = gg0;
        g_rowexp[row * 2 + 0] = b0;
        g_rowpos[row * 2 + 0] = p0;

        int p1 = atomicAdd(&g_cnt[b1], 1);
        g_rowlist[b1 * NB + p1] = row;
        g_gatelist[b1 * NB + p1] = gg1;
        g_rowexp[row * 2 + 1] = b1;
        g_rowpos[row * 2 + 1] = p1;
    }
}

// ---------------- row softmax * gate ----------------
__global__ __launch_bounds__(256)
void softmax_gate()
{
    const int e = blockIdx.x;
    const int warp = threadIdx.x >> 5, lane = threadIdx.x & 31;
    const int i = blockIdx.y * 8 + warp;
    if (i >= g_cnt[e]) return;
    const int slot = g_off[e] + i;
    float* P = &g_P[(size_t)slot * NC];

    float v[NC / 32];
    float mx = -INFINITY;
#pragma unroll
    for (int t = 0; t < NC / 32; t++) { v[t] = P[t * 32 + lane]; mx = fmaxf(mx, v[t]); }
#pragma unroll
    for (int o = 16; o > 0; o >>= 1) mx = fmaxf(mx, __shfl_xor_sync(0xffffffffu, mx, o));

    float sum = 0.0f;
#pragma unroll
    for (int t = 0; t < NC / 32; t++) { v[t] = expf(v[t] - mx); sum += v[t]; }
#pragma unroll
    for (int o = 16; o > 0; o >>= 1) sum += __shfl_xor_sync(0xffffffffu, sum, o);

    const float gt = g_gatelist[e * NB + i];
    const float inv = gt / sum;
#pragma unroll
    for (int t = 0; t < NC / 32; t++) P[t * 32 + lane] = v[t] * inv;
}

// ---------------- load-balance loss ----------------
__global__ __launch_bounds__(256)
void loss_kernel()
{
    const int e = threadIdx.x >> 5, lane = threadIdx.x & 31;
    float s = 0.0f;
    for (int r = lane; r < NB; r += 32) s += g_gates[r * NE + e];
#pragma unroll
    for (int o = 16; o > 0; o >>= 1) s += __shfl_xor_sync(0xffffffffu, s, o);

    __shared__ float imp[NE];
    if (lane == 0) imp[e] = s;
    __syncthreads();

    if (threadIdx.x == 0) {
        double mi = 0.0, ml = 0.0;
        for (int j = 0; j < NE; j++) { mi += (double)imp[j]; ml += (double)g_cnt[j]; }
        mi /= NE; ml /= NE;
        double vi = 0.0, vl = 0.0;
        for (int j = 0; j < NE; j++) {
            double di = (double)imp[j] - mi;  vi += di * di;
            double dl = (double)g_cnt[j] - ml; vl += dl * dl;
        }
        vi /= (NE - 1); vl /= (NE - 1);
        double loss = (vi / (mi * mi + 1e-10) + vl / (ml * ml + 1e-10)) * 0.01;
        g_loss = (float)loss;
    }
}

// ---------------- combine + log ----------------
__global__ __launch_bounds__(256)
void finalize_kernel(float* __restrict__ out, int out_size)
{
    const int row = blockIdx.x;
    const int e0 = g_rowexp[row * 2 + 0];
    const int e1 = g_rowexp[row * 2 + 1];
    const int s0 = g_off[e0] + g_rowpos[row * 2 + 0];
    const int s1 = g_off[e1] + g_rowpos[row * 2 + 1];
    const float* P0 = &g_P[(size_t)s0 * NC];
    const float* P1 = &g_P[(size_t)s1 * NC];
    for (int c = threadIdx.x; c < NC; c += 256) {
        float comb = P0[c] + P1[c];
        if (comb == 0.0f) comb = 2.2204460492503131e-16f;
        out[(size_t)row * NC + c] = logf(comb);
    }
    if (row == 0 && threadIdx.x == 0 && out_size > NB * NC)
        out[NB * NC] = g_loss;
}

// ---------------- launch ----------------
extern "C" void kernel_launch(void* const* d_in, const int* in_sizes, int n_in,
                              void* d_out, int out_size)
{
    const float* x   = (const float*)d_in[0];
    const float* x2  = (const float*)d_in[1];
    const float* Wg1 = (const float*)d_in[2];
    const float* bg1 = (const float*)d_in[3];
    const float* Wg2 = (const float*)d_in[4];
    const float* bg2 = (const float*)d_in[5];
    const float* W1  = (const float*)d_in[6];
    const float* b1  = (const float*)d_in[7];
    const float* W2  = (const float*)d_in[8];
    const float* b2  = (const float*)d_in[9];
    float* out = (float*)d_out;

    zero_counts<<<1, 32>>>();
    gemm0_split<<<dim3(NHG / 128, NB / 128), 256>>>(x, Wg1, bg1);
    gating_topk<<<NB / 8, 256>>>(Wg2, bg2);
    offsets_kernel<<<1, 32>>>();
    emma<1><<<dim3(NH / 128, NB / 128, NE), 256>>>(x2, W1, b1);
    emma<2><<<dim3(NC / 128, NB / 128, NE), 256>>>(nullptr, W2, b2);
    softmax_gate<<<dim3(NE, NB / 8), 256>>>();
    loss_kernel<<<1, 256>>>();
    finalize_kernel<<<NB, 256>>>(out, out_size);
}

// round 4
// speedup vs baseline: 4.5580x; 1.0008x over previous
#include <cuda_runtime.h>
#include <cuda_bf16.h>
#include <math.h>
#include <stdint.h>

// ---------------- problem constants ----------------
#define NB    4096
#define NDG   1024
#define NDI   1024
#define NHG   512
#define NE    8
#define NH    2048
#define NC    512
#define TEMPR 5.0f
#define NASSIGN (NB*2)

// ---------------- scratch ----------------
__device__ float g_hg[NB * NHG];
__device__ float g_gates[NB * NE];
__device__ int   g_cnt[NE];
__device__ int   g_off[NE];
__device__ int   g_rowlist[NE * NB];
__device__ float g_gatelist[NE * NB];
__device__ int   g_rowexp[NB * 2];
__device__ int   g_rowpos[NB * 2];
__device__ __nv_bfloat16 g_He[(size_t)NASSIGN * NH];
__device__ float g_P[(size_t)NASSIGN * NC];
__device__ float g_loss;

__global__ void zero_counts() {
    if (threadIdx.x < NE) g_cnt[threadIdx.x] = 0;
}
__global__ void offsets_kernel() {
    if (threadIdx.x == 0) {
        int o = 0;
        for (int e = 0; e < NE; e++) { g_off[e] = o; o += g_cnt[e]; }
    }
}

// ---------------- helpers ----------------
__device__ __forceinline__ uint32_t packbf(float a, float b) {
    __nv_bfloat162 h = __floats2bfloat162_rn(a, b);
    return *reinterpret_cast<uint32_t*>(&h);
}

__device__ __forceinline__ void mma_bf16(float* d, const uint32_t* a,
                                         const uint32_t* b, const float* c) {
    asm volatile(
        "mma.sync.aligned.m16n8k16.row.col.f32.bf16.bf16.f32 "
        "{%0,%1,%2,%3}, {%4,%5,%6,%7}, {%8,%9}, {%10,%11,%12,%13};\n"
        : "=f"(d[0]), "=f"(d[1]), "=f"(d[2]), "=f"(d[3])
        : "r"(a[0]), "r"(a[1]), "r"(a[2]), "r"(a[3]),
          "r"(b[0]), "r"(b[1]),
          "f"(c[0]), "f"(c[1]), "f"(c[2]), "f"(c[3]));
}

// ============================================================================
// Expert GEMMs, bf16 tensor cores.
// MODE 1: He = relu(gather(x2) @ W1[e] + b1[e])   M=cnt_e N=2048 K=1024
// MODE 2: P  = He @ W2[e] + b2[e]                 M=cnt_e N=512  K=2048
// SMEM: A as b32 k-pairs [m][kp] pad 20; B as b32 k-pair-interleaved [kp][n] pad 136.
// ============================================================================
template<int MODE>
__global__ __launch_bounds__(256, 2)
void emma(const float* __restrict__ Af,
          const float* __restrict__ Wall,
          const float* __restrict__ biasAll)
{
    constexpr int BM = 128, BK = 32;
    constexpr int LDA = 20, LDB = 136;

    const int e = blockIdx.z;
    const int M = g_cnt[e];
    const int m0 = blockIdx.y * BM;
    if (m0 >= M) return;
    const int n0 = blockIdx.x * 128;

    constexpr int Kd  = (MODE == 1) ? NDI : NH;
    constexpr int ldw = (MODE == 1) ? NH  : NC;
    const float* W    = Wall + (size_t)e * Kd * ldw;
    const float* bias = biasAll + e * ldw;
    const int* rowlist = g_rowlist + e * NB;
    const size_t offE = (size_t)g_off[e];
    const __nv_bfloat16* Ab = g_He + offE * NH;   // MODE 2 input

    __shared__ uint32_t As[2][BM][LDA];
    __shared__ uint32_t Bs[2][16][LDB];

    const int tid = threadIdx.x;
    // A gmem plan: 2 chunks of 8 k-values
    int arow[2], akc[2];
    size_t aoff[2];
#pragma unroll
    for (int c = 0; c < 2; c++) {
        int q = tid + 256 * c;
        arow[c] = q >> 2;
        akc[c]  = (q & 3) * 8;
        int gm = m0 + arow[c];
        if (MODE == 1) {
            int r = (gm < M) ? rowlist[gm] : rowlist[0];
            aoff[c] = (size_t)r * NDI;
        } else {
            int r = (gm < M) ? gm : 0;
            aoff[c] = (size_t)r * NH;
        }
    }
    // B gmem plan: 2 chunks of (2 k rows x 4 n)
    int bkp[2], bnq[2];
#pragma unroll
    for (int c = 0; c < 2; c++) {
        int q = tid + 256 * c;
        bkp[c] = q >> 5;
        bnq[c] = (q & 31) * 4;
    }

    const int warp = tid >> 5;
    const int wm = warp >> 1, wn = warp & 1;
    const int lane = tid & 31;
    const int g = lane >> 2, tg = lane & 3;

    float acc[2][8][4];
#pragma unroll
    for (int i = 0; i < 2; i++)
#pragma unroll
        for (int j = 0; j < 8; j++)
#pragma unroll
            for (int q = 0; q < 4; q++) acc[i][j][q] = 0.0f;

    float4 ra[2][2];
    uint4  rab[2];
    float4 rb[2][2];

    auto LDGt = [&](int k0) {
#pragma unroll
        for (int c = 0; c < 2; c++) {
            if (MODE == 1) {
                ra[c][0] = *(const float4*)(Af + aoff[c] + k0 + akc[c]);
                ra[c][1] = *(const float4*)(Af + aoff[c] + k0 + akc[c] + 4);
            } else {
                rab[c] = *(const uint4*)(Ab + aoff[c] + k0 + akc[c]);
            }
        }
#pragma unroll
        for (int c = 0; c < 2; c++) {
            rb[c][0] = *(const float4*)(W + (size_t)(k0 + 2 * bkp[c]) * ldw + n0 + bnq[c]);
            rb[c][1] = *(const float4*)(W + (size_t)(k0 + 2 * bkp[c] + 1) * ldw + n0 + bnq[c]);
        }
    };
    auto STSt = [&](int s) {
#pragma unroll
        for (int c = 0; c < 2; c++) {
            if (MODE == 1) {
                uint4 u;
                u.x = packbf(ra[c][0].x, ra[c][0].y);
                u.y = packbf(ra[c][0].z, ra[c][0].w);
                u.z = packbf(ra[c][1].x, ra[c][1].y);
                u.w = packbf(ra[c][1].z, ra[c][1].w);
                *(uint4*)&As[s][arow[c]][akc[c] >> 1] = u;
            } else {
                *(uint4*)&As[s][arow[c]][akc[c] >> 1] = rab[c];
            }
        }
#pragma unroll
        for (int c = 0; c < 2; c++) {
            uint4 u;
            u.x = packbf(rb[c][0].x, rb[c][1].x);
            u.y = packbf(rb[c][0].y, rb[c][1].y);
            u.z = packbf(rb[c][0].z, rb[c][1].z);
            u.w = packbf(rb[c][0].w, rb[c][1].w);
            *(uint4*)&Bs[s][bkp[c]][bnq[c]] = u;
        }
    };

    LDGt(0);
    STSt(0);
    __syncthreads();

    const int T = Kd / BK;
    for (int t = 0; t < T; t++) {
        const int s = t & 1;
        if (t + 1 < T) LDGt((t + 1) * BK);

#pragma unroll
        for (int ksub = 0; ksub < 2; ksub++) {
            const int kb = ksub * 8;
            uint32_t af[2][4];
#pragma unroll
            for (int mt = 0; mt < 2; mt++) {
                const int mr = wm * 32 + mt * 16;
                af[mt][0] = As[s][mr + g    ][kb + tg];
                af[mt][1] = As[s][mr + g + 8][kb + tg];
                af[mt][2] = As[s][mr + g    ][kb + tg + 4];
                af[mt][3] = As[s][mr + g + 8][kb + tg + 4];
            }
#pragma unroll
            for (int nt = 0; nt < 8; nt++) {
                const int nc = wn * 64 + nt * 8 + g;
                uint32_t bf[2];
                bf[0] = Bs[s][kb + tg    ][nc];
                bf[1] = Bs[s][kb + tg + 4][nc];
#pragma unroll
                for (int mt = 0; mt < 2; mt++)
                    mma_bf16(acc[mt][nt], af[mt], bf, acc[mt][nt]);
            }
        }

        if (t + 1 < T) {
            STSt((t + 1) & 1);
            __syncthreads();
        }
    }

    // epilogue
    __nv_bfloat16* Cb = g_He + offE * NH;   // MODE 1 out
    float*         Cf = g_P  + offE * NC;   // MODE 2 out
#pragma unroll
    for (int mt = 0; mt < 2; mt++) {
        const int gm1 = m0 + wm * 32 + mt * 16 + g;
        const int gm2 = gm1 + 8;
#pragma unroll
        for (int nt = 0; nt < 8; nt++) {
            const int col = n0 + wn * 64 + nt * 8 + tg * 2;
            const float b0 = bias[col], b1 = bias[col + 1];
            if (MODE == 1) {
                if (gm1 < M) {
                    float v0 = fmaxf(acc[mt][nt][0] + b0, 0.f);
                    float v1 = fmaxf(acc[mt][nt][1] + b1, 0.f);
                    *reinterpret_cast<__nv_bfloat162*>(Cb + (size_t)gm1 * NH + col) =
                        __floats2bfloat162_rn(v0, v1);
                }
                if (gm2 < M) {
                    float v0 = fmaxf(acc[mt][nt][2] + b0, 0.f);
                    float v1 = fmaxf(acc[mt][nt][3] + b1, 0.f);
                    *reinterpret_cast<__nv_bfloat162*>(Cb + (size_t)gm2 * NH + col) =
                        __floats2bfloat162_rn(v0, v1);
                }
            } else {
                if (gm1 < M)
                    *(float2*)(Cf + (size_t)gm1 * NC + col) =
                        make_float2(acc[mt][nt][0] + b0, acc[mt][nt][1] + b1);
                if (gm2 < M)
                    *(float2*)(Cf + (size_t)gm2 * NC + col) =
                        make_float2(acc[mt][nt][2] + b0, acc[mt][nt][3] + b1);
            }
        }
    }
}

// ============================================================================
// Gating layer 1: compensated bf16-split (hi*hi + hi*lo + lo*hi ~ fp32 acc).
// g_hg = relu(x @ Wg1 + bg1)   M=4096 N=512 K=1024. Single-buffered.
// ============================================================================
__global__ __launch_bounds__(256, 2)
void gemm0_split(const float* __restrict__ A,
                 const float* __restrict__ W,
                 const float* __restrict__ bias)
{
    constexpr int BM = 128, BK = 32;
    constexpr int LDA = 20, LDB = 136;
    constexpr int ldw = NHG;

    const int m0 = blockIdx.y * BM;
    const int n0 = blockIdx.x * 128;

    __shared__ uint32_t AsH[BM][LDA];
    __shared__ uint32_t AsL[BM][LDA];
    __shared__ uint32_t BsH[16][LDB];
    __shared__ uint32_t BsL[16][LDB];

    const int tid = threadIdx.x;
    int arow[2], akc[2];
    size_t aoff[2];
#pragma unroll
    for (int c = 0; c < 2; c++) {
        int q = tid + 256 * c;
        arow[c] = q >> 2;
        akc[c]  = (q & 3) * 8;
        aoff[c] = (size_t)(m0 + arow[c]) * NDG;
    }
    int bkp[2], bnq[2];
#pragma unroll
    for (int c = 0; c < 2; c++) {
        int q = tid + 256 * c;
        bkp[c] = q >> 5;
        bnq[c] = (q & 31) * 4;
    }

    const int warp = tid >> 5;
    const int wm = warp >> 1, wn = warp & 1;
    const int lane = tid & 31;
    const int g = lane >> 2, tg = lane & 3;

    float acc[2][8][4];
#pragma unroll
    for (int i = 0; i < 2; i++)
#pragma unroll
        for (int j = 0; j < 8; j++)
#pragma unroll
            for (int q = 0; q < 4; q++) acc[i][j][q] = 0.0f;

    auto splitpack = [](float a, float b, uint32_t& uh, uint32_t& ul) {
        __nv_bfloat16 ha = __float2bfloat16_rn(a);
        __nv_bfloat16 hb = __float2bfloat16_rn(b);
        float la = a - __bfloat162float(ha);
        float lb = b - __bfloat162float(hb);
        __nv_bfloat162 h2; h2.x = ha; h2.y = hb;
        uh = *reinterpret_cast<uint32_t*>(&h2);
        ul = packbf(la, lb);
    };

    const int T = NDG / BK;
    for (int t = 0; t < T; t++) {
        const int k0 = t * BK;
        float4 ra[2][2], rb[2][2];
#pragma unroll
        for (int c = 0; c < 2; c++) {
            ra[c][0] = *(const float4*)(A + aoff[c] + k0 + akc[c]);
            ra[c][1] = *(const float4*)(A + aoff[c] + k0 + akc[c] + 4);
            rb[c][0] = *(const float4*)(W + (size_t)(k0 + 2 * bkp[c]) * ldw + n0 + bnq[c]);
            rb[c][1] = *(const float4*)(W + (size_t)(k0 + 2 * bkp[c] + 1) * ldw + n0 + bnq[c]);
        }
        __syncthreads();   // previous tile fully consumed
#pragma unroll
        for (int c = 0; c < 2; c++) {
            uint4 uh, ul;
            splitpack(ra[c][0].x, ra[c][0].y, uh.x, ul.x);
            splitpack(ra[c][0].z, ra[c][0].w, uh.y, ul.y);
            splitpack(ra[c][1].x, ra[c][1].y, uh.z, ul.z);
            splitpack(ra[c][1].z, ra[c][1].w, uh.w, ul.w);
            *(uint4*)&AsH[arow[c]][akc[c] >> 1] = uh;
            *(uint4*)&AsL[arow[c]][akc[c] >> 1] = ul;
        }
#pragma unroll
        for (int c = 0; c < 2; c++) {
            uint4 uh, ul;
            splitpack(rb[c][0].x, rb[c][1].x, uh.x, ul.x);
            splitpack(rb[c][0].y, rb[c][1].y, uh.y, ul.y);
            splitpack(rb[c][0].z, rb[c][1].z, uh.z, ul.z);
            splitpack(rb[c][0].w, rb[c][1].w, uh.w, ul.w);
            *(uint4*)&BsH[bkp[c]][bnq[c]] = uh;
            *(uint4*)&BsL[bkp[c]][bnq[c]] = ul;
        }
        __syncthreads();

#pragma unroll
        for (int ksub = 0; ksub < 2; ksub++) {
            const int kb = ksub * 8;
            uint32_t afh[2][4], afl[2][4];
#pragma unroll
            for (int mt = 0; mt < 2; mt++) {
                const int mr = wm * 32 + mt * 16;
                afh[mt][0] = AsH[mr + g    ][kb + tg];
                afh[mt][1] = AsH[mr + g + 8][kb + tg];
                afh[mt][2] = AsH[mr + g    ][kb + tg + 4];
                afh[mt][3] = AsH[mr + g + 8][kb + tg + 4];
                afl[mt][0] = AsL[mr + g    ][kb + tg];
                afl[mt][1] = AsL[mr + g + 8][kb + tg];
                afl[mt][2] = AsL[mr + g    ][kb + tg + 4];
                afl[mt][3] = AsL[mr + g + 8][kb + tg + 4];
            }
#pragma unroll
            for (int nt = 0; nt < 8; nt++) {
                const int nc = wn * 64 + nt * 8 + g;
                uint32_t bfh[2], bfl[2];
                bfh[0] = BsH[kb + tg    ][nc];
                bfh[1] = BsH[kb + tg + 4][nc];
                bfl[0] = BsL[kb + tg    ][nc];
                bfl[1] = BsL[kb + tg + 4][nc];
#pragma unroll
                for (int mt = 0; mt < 2; mt++) {
                    mma_bf16(acc[mt][nt], afh[mt], bfh, acc[mt][nt]);
                    mma_bf16(acc[mt][nt], afh[mt], bfl, acc[mt][nt]);
                    mma_bf16(acc[mt][nt], afl[mt], bfh, acc[mt][nt]);
                }
            }
        }
    }

#pragma unroll
    for (int mt = 0; mt < 2; mt++) {
        const int gm1 = m0 + wm * 32 + mt * 16 + g;
        const int gm2 = gm1 + 8;
#pragma unroll
        for (int nt = 0; nt < 8; nt++) {
            const int col = n0 + wn * 64 + nt * 8 + tg * 2;
            const float b0 = bias[col], b1 = bias[col + 1];
            *(float2*)(g_hg + (size_t)gm1 * NHG + col) =
                make_float2(fmaxf(acc[mt][nt][0] + b0, 0.f), fmaxf(acc[mt][nt][1] + b1, 0.f));
            *(float2*)(g_hg + (size_t)gm2 * NHG + col) =
                make_float2(fmaxf(acc[mt][nt][2] + b0, 0.f), fmaxf(acc[mt][nt][3] + b1, 0.f));
        }
    }
}

// ---------------- gating layer 2 + top-2 + dispatch ----------------
__global__ __launch_bounds__(256)
void gating_topk(const float* __restrict__ Wg2, const float* __restrict__ bg2)
{
    __shared__ float sW[NE][NHG];
    __shared__ float sb[NE];
    const int tid = threadIdx.x;
    for (int i = tid; i < NE * NHG; i += 256) {
        int j = i >> 9;
        int h = i & (NHG - 1);
        sW[j][h] = Wg2[h * NE + j];
    }
    if (tid < NE) sb[tid] = bg2[tid];
    __syncthreads();

    const int warp = tid >> 5, lane = tid & 31;
    const int row = blockIdx.x * 8 + warp;

    float acc[NE];
#pragma unroll
    for (int j = 0; j < NE; j++) acc[j] = 0.0f;

    const float* hr = &g_hg[(size_t)row * NHG];
#pragma unroll 4
    for (int t = 0; t < NHG / 32; t++) {
        float v = hr[t * 32 + lane];
#pragma unroll
        for (int j = 0; j < NE; j++) acc[j] = fmaf(v, sW[j][t * 32 + lane], acc[j]);
    }
#pragma unroll
    for (int j = 0; j < NE; j++)
#pragma unroll
        for (int o = 16; o > 0; o >>= 1)
            acc[j] += __shfl_xor_sync(0xffffffffu, acc[j], o);

    if (lane == 0) {
        float lg[NE];
#pragma unroll
        for (int j = 0; j < NE; j++) lg[j] = acc[j] + sb[j];

        int b0 = 0; float v0 = lg[0];
#pragma unroll
        for (int j = 1; j < NE; j++) if (lg[j] > v0) { v0 = lg[j]; b0 = j; }
        int b1 = -1; float v1 = -INFINITY;
#pragma unroll
        for (int j = 0; j < NE; j++) if (j != b0 && lg[j] > v1) { v1 = lg[j]; b1 = j; }

        float e1 = expf((v1 - v0) / TEMPR);
        float s = 1.0f + e1;
        float gg0 = 1.0f / s, gg1 = e1 / s;

#pragma unroll
        for (int j = 0; j < NE; j++) g_gates[row * NE + j] = 0.0f;
        g_gates[row * NE + b0] = gg0;
        g_gates[row * NE + b1] = gg1;

        int p0 = atomicAdd(&g_cnt[b0], 1);
        g_rowlist[b0 * NB + p0] = row;
        g_gatelist[b0 * NB + p0] = gg0;
        g_rowexp[row * 2 + 0] = b0;
        g_rowpos[row * 2 + 0] = p0;

        int p1 = atomicAdd(&g_cnt[b1], 1);
        g_rowlist[b1 * NB + p1] = row;
        g_gatelist[b1 * NB + p1] = gg1;
        g_rowexp[row * 2 + 1] = b1;
        g_rowpos[row * 2 + 1] = p1;
    }
}

// ---------------- row softmax * gate ----------------
__global__ __launch_bounds__(256)
void softmax_gate()
{
    const int e = blockIdx.x;
    const int warp = threadIdx.x >> 5, lane = threadIdx.x & 31;
    const int i = blockIdx.y * 8 + warp;
    if (i >= g_cnt[e]) return;
    const int slot = g_off[e] + i;
    float* P = &g_P[(size_t)slot * NC];

    float v[NC / 32];
    float mx = -INFINITY;
#pragma unroll
    for (int t = 0; t < NC / 32; t++) { v[t] = P[t * 32 + lane]; mx = fmaxf(mx, v[t]); }
#pragma unroll
    for (int o = 16; o > 0; o >>= 1) mx = fmaxf(mx, __shfl_xor_sync(0xffffffffu, mx, o));

    float sum = 0.0f;
#pragma unroll
    for (int t = 0; t < NC / 32; t++) { v[t] = expf(v[t] - mx); sum += v[t]; }
#pragma unroll
    for (int o = 16; o > 0; o >>= 1) sum += __shfl_xor_sync(0xffffffffu, sum, o);

    const float gt = g_gatelist[e * NB + i];
    const float inv = gt / sum;
#pragma unroll
    for (int t = 0; t < NC / 32; t++) P[t * 32 + lane] = v[t] * inv;
}

// ---------------- load-balance loss ----------------
__global__ __launch_bounds__(256)
void loss_kernel()
{
    const int e = threadIdx.x >> 5, lane = threadIdx.x & 31;
    float s = 0.0f;
    for (int r = lane; r < NB; r += 32) s += g_gates[r * NE + e];
#pragma unroll
    for (int o = 16; o > 0; o >>= 1) s += __shfl_xor_sync(0xffffffffu, s, o);

    __shared__ float imp[NE];
    if (lane == 0) imp[e] = s;
    __syncthreads();

    if (threadIdx.x == 0) {
        double mi = 0.0, ml = 0.0;
        for (int j = 0; j < NE; j++) { mi += (double)imp[j]; ml += (double)g_cnt[j]; }
        mi /= NE; ml /= NE;
        double vi = 0.0, vl = 0.0;
        for (int j = 0; j < NE; j++) {
            double di = (double)imp[j] - mi;  vi += di * di;
            double dl = (double)g_cnt[j] - ml; vl += dl * dl;
        }
        vi /= (NE - 1); vl /= (NE - 1);
        double loss = (vi / (mi * mi + 1e-10) + vl / (ml * ml + 1e-10)) * 0.01;
        g_loss = (float)loss;
    }
}

// ---------------- combine + log ----------------
__global__ __launch_bounds__(256)
void finalize_kernel(float* __restrict__ out, int out_size)
{
    const int row = blockIdx.x;
    const int e0 = g_rowexp[row * 2 + 0];
    const int e1 = g_rowexp[row * 2 + 1];
    const int s0 = g_off[e0] + g_rowpos[row * 2 + 0];
    const int s1 = g_off[e1] + g_rowpos[row * 2 + 1];
    const float* P0 = &g_P[(size_t)s0 * NC];
    const float* P1 = &g_P[(size_t)s1 * NC];
    for (int c = threadIdx.x; c < NC; c += 256) {
        float comb = P0[c] + P1[c];
        if (comb == 0.0f) comb = 2.2204460492503131e-16f;
        out[(size_t)row * NC + c] = logf(comb);
    }
    if (row == 0 && threadIdx.x == 0 && out_size > NB * NC)
        out[NB * NC] = g_loss;
}

// ---------------- launch ----------------
extern "C" void kernel_launch(void* const* d_in, const int* in_sizes, int n_in,
                              void* d_out, int out_size)
{
    const float* x   = (const float*)d_in[0];
    const float* x2  = (const float*)d_in[1];
    const float* Wg1 = (const float*)d_in[2];
    const float* bg1 = (const float*)d_in[3];
    const float* Wg2 = (const float*)d_in[4];
    const float* bg2 = (const float*)d_in[5];
    const float* W1  = (const float*)d_in[6];
    const float* b1  = (const float*)d_in[7];
    const float* W2  = (const float*)d_in[8];
    const float* b2  = (const float*)d_in[9];
    float* out = (float*)d_out;

    zero_counts<<<1, 32>>>();
    gemm0_split<<<dim3(NHG / 128, NB / 128), 256>>>(x, Wg1, bg1);
    gating_topk<<<NB / 8, 256>>>(Wg2, bg2);
    offsets_kernel<<<1, 32>>>();
    emma<1><<<dim3(NH / 128, NB / 128, NE), 256>>>(x2, W1, b1);
    emma<2><<<dim3(NC / 128, NB / 128, NE), 256>>>(nullptr, W2, b2);
    softmax_gate<<<dim3(NE, NB / 8), 256>>>();
    loss_kernel<<<1, 256>>>();
    finalize_kernel<<<NB, 256>>>(out, out_size);
}

// round 7
// speedup vs baseline: 4.5688x; 1.0024x over previous
#include <cuda_runtime.h>
#include <cuda_fp16.h>
#include <cuda_bf16.h>
#include <math.h>
#include <stdint.h>

// ---------------- problem constants ----------------
#define NB    4096
#define NDG   1024
#define NDI   1024
#define NHG   512
#define NE    8
#define NH    2048
#define NC    512
#define TEMPR 5.0f
#define NASSIGN (NB*2)

// ---------------- scratch ----------------
__device__ float g_hg[NB * NHG];
__device__ float g_gates[NB * NE];
__device__ int   g_cnt[NE];
__device__ int   g_off[NE];
__device__ int   g_rowlist[NE * NB];
__device__ float g_gatelist[NE * NB];
__device__ int   g_rowexp[NB * 2];
__device__ int   g_rowpos[NB * 2];
__device__ __half g_He[(size_t)NASSIGN * NH];
__device__ float g_P[(size_t)NASSIGN * NC];
__device__ float g_loss;

__global__ void zero_counts() {
    if (threadIdx.x < NE) g_cnt[threadIdx.x] = 0;
}
__global__ void offsets_kernel() {
    if (threadIdx.x == 0) {
        int o = 0;
        for (int e = 0; e < NE; e++) { g_off[e] = o; o += g_cnt[e]; }
    }
}

// ---------------- helpers ----------------
__device__ __forceinline__ uint32_t packbf(float a, float b) {
    __nv_bfloat162 h = __floats2bfloat162_rn(a, b);
    return *reinterpret_cast<uint32_t*>(&h);
}
__device__ __forceinline__ uint32_t packh(float a, float b) {
    __half2 h = __floats2half2_rn(a, b);
    return *reinterpret_cast<uint32_t*>(&h);
}

__device__ __forceinline__ void mma_bf16(float* d, const uint32_t* a,
                                         const uint32_t* b, const float* c) {
    asm volatile(
        "mma.sync.aligned.m16n8k16.row.col.f32.bf16.bf16.f32 "
        "{%0,%1,%2,%3}, {%4,%5,%6,%7}, {%8,%9}, {%10,%11,%12,%13};\n"
        : "=f"(d[0]), "=f"(d[1]), "=f"(d[2]), "=f"(d[3])
        : "r"(a[0]), "r"(a[1]), "r"(a[2]), "r"(a[3]),
          "r"(b[0]), "r"(b[1]),
          "f"(c[0]), "f"(c[1]), "f"(c[2]), "f"(c[3]));
}
__device__ __forceinline__ void mma_fp16(float* d, const uint32_t* a,
                                         const uint32_t* b, const float* c) {
    asm volatile(
        "mma.sync.aligned.m16n8k16.row.col.f32.f16.f16.f32 "
        "{%0,%1,%2,%3}, {%4,%5,%6,%7}, {%8,%9}, {%10,%11,%12,%13};\n"
        : "=f"(d[0]), "=f"(d[1]), "=f"(d[2]), "=f"(d[3])
        : "r"(a[0]), "r"(a[1]), "r"(a[2]), "r"(a[3]),
          "r"(b[0]), "r"(b[1]),
          "f"(c[0]), "f"(c[1]), "f"(c[2]), "f"(c[3]));
}

// ============================================================================
// Expert GEMMs, fp16 tensor cores (R3 skeleton, dtype change only).
// MODE 1: He = relu(gather(x2) @ W1[e] + b1[e])   M=cnt_e N=2048 K=1024
// MODE 2: P  = He @ W2[e] + b2[e]                 M=cnt_e N=512  K=2048
// SMEM: A as u32 k-pairs [m][kp] pad 20; B as u32 k-pair-interleaved [kp][n] pad 136.
// ============================================================================
template<int MODE>
__global__ __launch_bounds__(256, 2)
void emma(const float* __restrict__ Af,
          const float* __restrict__ Wall,
          const float* __restrict__ biasAll)
{
    constexpr int BM = 128, BK = 32;
    constexpr int LDA = 20, LDB = 136;

    const int e = blockIdx.z;
    const int M = g_cnt[e];
    const int m0 = blockIdx.y * BM;
    if (m0 >= M) return;
    const int n0 = blockIdx.x * 128;

    constexpr int Kd  = (MODE == 1) ? NDI : NH;
    constexpr int ldw = (MODE == 1) ? NH  : NC;
    const float* W    = Wall + (size_t)e * Kd * ldw;
    const float* bias = biasAll + e * ldw;
    const int* rowlist = g_rowlist + e * NB;
    const size_t offE = (size_t)g_off[e];
    const __half* Ab = g_He + offE * NH;   // MODE 2 input

    __shared__ uint32_t As[2][BM][LDA];
    __shared__ uint32_t Bs[2][16][LDB];

    const int tid = threadIdx.x;
    // A gmem plan: 2 chunks of 8 k-values
    int arow[2], akc[2];
    size_t aoff[2];
#pragma unroll
    for (int c = 0; c < 2; c++) {
        int q = tid + 256 * c;
        arow[c] = q >> 2;
        akc[c]  = (q & 3) * 8;
        int gm = m0 + arow[c];
        if (MODE == 1) {
            int r = (gm < M) ? rowlist[gm] : rowlist[0];
            aoff[c] = (size_t)r * NDI;
        } else {
            int r = (gm < M) ? gm : 0;
            aoff[c] = (size_t)r * NH;
        }
    }
    // B gmem plan: 2 chunks of (2 k rows x 4 n)
    int bkp[2], bnq[2];
#pragma unroll
    for (int c = 0; c < 2; c++) {
        int q = tid + 256 * c;
        bkp[c] = q >> 5;
        bnq[c] = (q & 31) * 4;
    }

    const int warp = tid >> 5;
    const int wm = warp >> 1, wn = warp & 1;
    const int lane = tid & 31;
    const int g = lane >> 2, tg = lane & 3;

    float acc[2][8][4];
#pragma unroll
    for (int i = 0; i < 2; i++)
#pragma unroll
        for (int j = 0; j < 8; j++)
#pragma unroll
            for (int q = 0; q < 4; q++) acc[i][j][q] = 0.0f;

    float4 ra[2][2];
    uint4  rab[2];
    float4 rb[2][2];

    auto LDGt = [&](int k0) {
#pragma unroll
        for (int c = 0; c < 2; c++) {
            if (MODE == 1) {
                ra[c][0] = *(const float4*)(Af + aoff[c] + k0 + akc[c]);
                ra[c][1] = *(const float4*)(Af + aoff[c] + k0 + akc[c] + 4);
            } else {
                rab[c] = *(const uint4*)(Ab + aoff[c] + k0 + akc[c]);
            }
        }
#pragma unroll
        for (int c = 0; c < 2; c++) {
            rb[c][0] = *(const float4*)(W + (size_t)(k0 + 2 * bkp[c]) * ldw + n0 + bnq[c]);
            rb[c][1] = *(const float4*)(W + (size_t)(k0 + 2 * bkp[c] + 1) * ldw + n0 + bnq[c]);
        }
    };
    auto STSt = [&](int s) {
#pragma unroll
        for (int c = 0; c < 2; c++) {
            if (MODE == 1) {
                uint4 u;
                u.x = packh(ra[c][0].x, ra[c][0].y);
                u.y = packh(ra[c][0].z, ra[c][0].w);
                u.z = packh(ra[c][1].x, ra[c][1].y);
                u.w = packh(ra[c][1].z, ra[c][1].w);
                *(uint4*)&As[s][arow[c]][akc[c] >> 1] = u;
            } else {
                *(uint4*)&As[s][arow[c]][akc[c] >> 1] = rab[c];
            }
        }
#pragma unroll
        for (int c = 0; c < 2; c++) {
            uint4 u;
            u.x = packh(rb[c][0].x, rb[c][1].x);
            u.y = packh(rb[c][0].y, rb[c][1].y);
            u.z = packh(rb[c][0].z, rb[c][1].z);
            u.w = packh(rb[c][0].w, rb[c][1].w);
            *(uint4*)&Bs[s][bkp[c]][bnq[c]] = u;
        }
    };

    LDGt(0);
    STSt(0);
    __syncthreads();

    const int T = Kd / BK;
    for (int t = 0; t < T; t++) {
        const int s = t & 1;
        if (t + 1 < T) LDGt((t + 1) * BK);

#pragma unroll
        for (int ksub = 0; ksub < 2; ksub++) {
            const int kb = ksub * 8;
            uint32_t af[2][4];
#pragma unroll
            for (int mt = 0; mt < 2; mt++) {
                const int mr = wm * 32 + mt * 16;
                af[mt][0] = As[s][mr + g    ][kb + tg];
                af[mt][1] = As[s][mr + g + 8][kb + tg];
                af[mt][2] = As[s][mr + g    ][kb + tg + 4];
                af[mt][3] = As[s][mr + g + 8][kb + tg + 4];
            }
#pragma unroll
            for (int nt = 0; nt < 8; nt++) {
                const int nc = wn * 64 + nt * 8 + g;
                uint32_t bf[2];
                bf[0] = Bs[s][kb + tg    ][nc];
                bf[1] = Bs[s][kb + tg + 4][nc];
#pragma unroll
                for (int mt = 0; mt < 2; mt++)
                    mma_fp16(acc[mt][nt], af[mt], bf, acc[mt][nt]);
            }
        }

        if (t + 1 < T) {
            STSt((t + 1) & 1);
            __syncthreads();
        }
    }

    // epilogue
    __half* Ch = g_He + offE * NH;   // MODE 1 out
    float*  Cf = g_P  + offE * NC;   // MODE 2 out
#pragma unroll
    for (int mt = 0; mt < 2; mt++) {
        const int gm1 = m0 + wm * 32 + mt * 16 + g;
        const int gm2 = gm1 + 8;
#pragma unroll
        for (int nt = 0; nt < 8; nt++) {
            const int col = n0 + wn * 64 + nt * 8 + tg * 2;
            const float b0 = bias[col], b1 = bias[col + 1];
            if (MODE == 1) {
                if (gm1 < M) {
                    float v0 = fmaxf(acc[mt][nt][0] + b0, 0.f);
                    float v1 = fmaxf(acc[mt][nt][1] + b1, 0.f);
                    *(uint32_t*)(Ch + (size_t)gm1 * NH + col) = packh(v0, v1);
                }
                if (gm2 < M) {
                    float v0 = fmaxf(acc[mt][nt][2] + b0, 0.f);
                    float v1 = fmaxf(acc[mt][nt][3] + b1, 0.f);
                    *(uint32_t*)(Ch + (size_t)gm2 * NH + col) = packh(v0, v1);
                }
            } else {
                if (gm1 < M)
                    *(float2*)(Cf + (size_t)gm1 * NC + col) =
                        make_float2(acc[mt][nt][0] + b0, acc[mt][nt][1] + b1);
                if (gm2 < M)
                    *(float2*)(Cf + (size_t)gm2 * NC + col) =
                        make_float2(acc[mt][nt][2] + b0, acc[mt][nt][3] + b1);
            }
        }
    }
}

// ============================================================================
// Gating layer 1: compensated bf16-split — BYTE-IDENTICAL to the passing R3.
// g_hg = relu(x @ Wg1 + bg1)   M=4096 N=512 K=1024
// ============================================================================
__global__ __launch_bounds__(256, 2)
void gemm0_split(const float* __restrict__ A,
                 const float* __restrict__ W,
                 const float* __restrict__ bias)
{
    constexpr int BM = 128, BK = 32;
    constexpr int LDA = 20, LDB = 136;
    constexpr int ldw = NHG;

    const int m0 = blockIdx.y * BM;
    const int n0 = blockIdx.x * 128;

    __shared__ uint32_t AsH[BM][LDA];
    __shared__ uint32_t AsL[BM][LDA];
    __shared__ uint32_t BsH[16][LDB];
    __shared__ uint32_t BsL[16][LDB];

    const int tid = threadIdx.x;
    int arow[2], akc[2];
    size_t aoff[2];
#pragma unroll
    for (int c = 0; c < 2; c++) {
        int q = tid + 256 * c;
        arow[c] = q >> 2;
        akc[c]  = (q & 3) * 8;
        aoff[c] = (size_t)(m0 + arow[c]) * NDG;
    }
    int bkp[2], bnq[2];
#pragma unroll
    for (int c = 0; c < 2; c++) {
        int q = tid + 256 * c;
        bkp[c] = q >> 5;
        bnq[c] = (q & 31) * 4;
    }

    const int warp = tid >> 5;
    const int wm = warp >> 1, wn = warp & 1;
    const int lane = tid & 31;
    const int g = lane >> 2, tg = lane & 3;

    float acc[2][8][4];
#pragma unroll
    for (int i = 0; i < 2; i++)
#pragma unroll
        for (int j = 0; j < 8; j++)
#pragma unroll
            for (int q = 0; q < 4; q++) acc[i][j][q] = 0.0f;

    auto splitpack = [](float a, float b, uint32_t& uh, uint32_t& ul) {
        __nv_bfloat16 ha = __float2bfloat16_rn(a);
        __nv_bfloat16 hb = __float2bfloat16_rn(b);
        float la = a - __bfloat162float(ha);
        float lb = b - __bfloat162float(hb);
        __nv_bfloat162 h2; h2.x = ha; h2.y = hb;
        uh = *reinterpret_cast<uint32_t*>(&h2);
        ul = packbf(la, lb);
    };

    const int T = NDG / BK;
    for (int t = 0; t < T; t++) {
        const int k0 = t * BK;
        float4 ra[2][2], rb[2][2];
#pragma unroll
        for (int c = 0; c < 2; c++) {
            ra[c][0] = *(const float4*)(A + aoff[c] + k0 + akc[c]);
            ra[c][1] = *(const float4*)(A + aoff[c] + k0 + akc[c] + 4);
            rb[c][0] = *(const float4*)(W + (size_t)(k0 + 2 * bkp[c]) * ldw + n0 + bnq[c]);
            rb[c][1] = *(const float4*)(W + (size_t)(k0 + 2 * bkp[c] + 1) * ldw + n0 + bnq[c]);
        }
        __syncthreads();
#pragma unroll
        for (int c = 0; c < 2; c++) {
            uint4 uh, ul;
            splitpack(ra[c][0].x, ra[c][0].y, uh.x, ul.x);
            splitpack(ra[c][0].z, ra[c][0].w, uh.y, ul.y);
            splitpack(ra[c][1].x, ra[c][1].y, uh.z, ul.z);
            splitpack(ra[c][1].z, ra[c][1].w, uh.w, ul.w);
            *(uint4*)&AsH[arow[c]][akc[c] >> 1] = uh;
            *(uint4*)&AsL[arow[c]][akc[c] >> 1] = ul;
        }
#pragma unroll
        for (int c = 0; c < 2; c++) {
            uint4 uh, ul;
            splitpack(rb[c][0].x, rb[c][1].x, uh.x, ul.x);
            splitpack(rb[c][0].y, rb[c][1].y, uh.y, ul.y);
            splitpack(rb[c][0].z, rb[c][1].z, uh.z, ul.z);
            splitpack(rb[c][0].w, rb[c][1].w, uh.w, ul.w);
            *(uint4*)&BsH[bkp[c]][bnq[c]] = uh;
            *(uint4*)&BsL[bkp[c]][bnq[c]] = ul;
        }
        __syncthreads();

#pragma unroll
        for (int ksub = 0; ksub < 2; ksub++) {
            const int kb = ksub * 8;
            uint32_t afh[2][4], afl[2][4];
#pragma unroll
            for (int mt = 0; mt < 2; mt++) {
                const int mr = wm * 32 + mt * 16;
                afh[mt][0] = AsH[mr + g    ][kb + tg];
                afh[mt][1] = AsH[mr + g + 8][kb + tg];
                afh[mt][2] = AsH[mr + g    ][kb + tg + 4];
                afh[mt][3] = AsH[mr + g + 8][kb + tg + 4];
                afl[mt][0] = AsL[mr + g    ][kb + tg];
                afl[mt][1] = AsL[mr + g + 8][kb + tg];
                afl[mt][2] = AsL[mr + g    ][kb + tg + 4];
                afl[mt][3] = AsL[mr + g + 8][kb + tg + 4];
            }
#pragma unroll
            for (int nt = 0; nt < 8; nt++) {
                const int nc = wn * 64 + nt * 8 + g;
                uint32_t bfh[2], bfl[2];
                bfh[0] = BsH[kb + tg    ][nc];
                bfh[1] = BsH[kb + tg + 4][nc];
                bfl[0] = BsL[kb + tg    ][nc];
                bfl[1] = BsL[kb + tg + 4][nc];
#pragma unroll
                for (int mt = 0; mt < 2; mt++) {
                    mma_bf16(acc[mt][nt], afh[mt], bfh, acc[mt][nt]);
                    mma_bf16(acc[mt][nt], afh[mt], bfl, acc[mt][nt]);
                    mma_bf16(acc[mt][nt], afl[mt], bfh, acc[mt][nt]);
                }
            }
        }
    }

#pragma unroll
    for (int mt = 0; mt < 2; mt++) {
        const int gm1 = m0 + wm * 32 + mt * 16 + g;
        const int gm2 = gm1 + 8;
#pragma unroll
        for (int nt = 0; nt < 8; nt++) {
            const int col = n0 + wn * 64 + nt * 8 + tg * 2;
            const float b0 = bias[col], b1 = bias[col + 1];
            *(float2*)(g_hg + (size_t)gm1 * NHG + col) =
                make_float2(fmaxf(acc[mt][nt][0] + b0, 0.f), fmaxf(acc[mt][nt][1] + b1, 0.f));
            *(float2*)(g_hg + (size_t)gm2 * NHG + col) =
                make_float2(fmaxf(acc[mt][nt][2] + b0, 0.f), fmaxf(acc[mt][nt][3] + b1, 0.f));
        }
    }
}

// ---------------- gating layer 2 + top-2 + dispatch ----------------
__global__ __launch_bounds__(256)
void gating_topk(const float* __restrict__ Wg2, const float* __restrict__ bg2)
{
    __shared__ float sW[NE][NHG];
    __shared__ float sb[NE];
    const int tid = threadIdx.x;
    for (int i = tid; i < NE * NHG; i += 256)
        sW[i >> 9][i & (NHG - 1)] = Wg2[(i & (NHG - 1)) * NE + (i >> 9)];
    if (tid < NE) sb[tid] = bg2[tid];
    __syncthreads();

    const int warp = tid >> 5, lane = tid & 31;
    const int row = blockIdx.x * 8 + warp;

    float acc[NE];
#pragma unroll
    for (int j = 0; j < NE; j++) acc[j] = 0.0f;
    const float* hr = &g_hg[(size_t)row * NHG];
#pragma unroll 4
    for (int t = 0; t < NHG / 32; t++) {
        float v = hr[t * 32 + lane];
#pragma unroll
        for (int j = 0; j < NE; j++) acc[j] = fmaf(v, sW[j][t * 32 + lane], acc[j]);
    }
#pragma unroll
    for (int j = 0; j < NE; j++)
#pragma unroll
        for (int o = 16; o > 0; o >>= 1)
            acc[j] += __shfl_xor_sync(0xffffffffu, acc[j], o);

    if (lane == 0) {
        float lg[NE];
#pragma unroll
        for (int j = 0; j < NE; j++) lg[j] = acc[j] + sb[j];
        int b0 = 0; float v0 = lg[0];
#pragma unroll
        for (int j = 1; j < NE; j++) if (lg[j] > v0) { v0 = lg[j]; b0 = j; }
        int b1 = -1; float v1 = -INFINITY;
#pragma unroll
        for (int j = 0; j < NE; j++) if (j != b0 && lg[j] > v1) { v1 = lg[j]; b1 = j; }

        float e1 = expf((v1 - v0) / TEMPR);
        float s = 1.0f + e1;
        float gg0 = 1.0f / s, gg1 = e1 / s;
#pragma unroll
        for (int j = 0; j < NE; j++) g_gates[row * NE + j] = 0.0f;
        g_gates[row * NE + b0] = gg0;
        g_gates[row * NE + b1] = gg1;

        int p0 = atomicAdd(&g_cnt[b0], 1);
        g_rowlist[b0 * NB + p0] = row;
        g_gatelist[b0 * NB + p0] = gg0;
        g_rowexp[row * 2 + 0] = b0;
        g_rowpos[row * 2 + 0] = p0;
        int p1 = atomicAdd(&g_cnt[b1], 1);
        g_rowlist[b1 * NB + p1] = row;
        g_gatelist[b1 * NB + p1] = gg1;
        g_rowexp[row * 2 + 1] = b1;
        g_rowpos[row * 2 + 1] = p1;
    }
}

// ---------------- row softmax * gate ----------------
__global__ __launch_bounds__(256)
void softmax_gate()
{
    const int e = blockIdx.x;
    const int warp = threadIdx.x >> 5, lane = threadIdx.x & 31;
    const int i = blockIdx.y * 8 + warp;
    if (i >= g_cnt[e]) return;
    float* P = &g_P[(size_t)(g_off[e] + i) * NC];

    float v[NC / 32];
    float mx = -INFINITY;
#pragma unroll
    for (int t = 0; t < NC / 32; t++) { v[t] = P[t * 32 + lane]; mx = fmaxf(mx, v[t]); }
#pragma unroll
    for (int o = 16; o > 0; o >>= 1) mx = fmaxf(mx, __shfl_xor_sync(0xffffffffu, mx, o));
    float sum = 0.0f;
#pragma unroll
    for (int t = 0; t < NC / 32; t++) { v[t] = expf(v[t] - mx); sum += v[t]; }
#pragma unroll
    for (int o = 16; o > 0; o >>= 1) sum += __shfl_xor_sync(0xffffffffu, sum, o);
    const float inv = g_gatelist[e * NB + i] / sum;
#pragma unroll
    for (int t = 0; t < NC / 32; t++) P[t * 32 + lane] = v[t] * inv;
}

// ---------------- load-balance loss ----------------
__global__ __launch_bounds__(256)
void loss_kernel()
{
    const int e = threadIdx.x >> 5, lane = threadIdx.x & 31;
    float s = 0.0f;
    for (int r = lane; r < NB; r += 32) s += g_gates[r * NE + e];
#pragma unroll
    for (int o = 16; o > 0; o >>= 1) s += __shfl_xor_sync(0xffffffffu, s, o);
    __shared__ float imp[NE];
    if (lane == 0) imp[e] = s;
    __syncthreads();
    if (threadIdx.x == 0) {
        double mi = 0.0, ml = 0.0;
        for (int j = 0; j < NE; j++) { mi += (double)imp[j]; ml += (double)g_cnt[j]; }
        mi /= NE; ml /= NE;
        double vi = 0.0, vl = 0.0;
        for (int j = 0; j < NE; j++) {
            double di = (double)imp[j] - mi;  vi += di * di;
            double dl = (double)g_cnt[j] - ml; vl += dl * dl;
        }
        vi /= (NE - 1); vl /= (NE - 1);
        g_loss = (float)((vi / (mi * mi + 1e-10) + vl / (ml * ml + 1e-10)) * 0.01);
    }
}

// ---------------- combine + log ----------------
__global__ __launch_bounds__(256)
void finalize_kernel(float* __restrict__ out, int out_size)
{
    const int row = blockIdx.x;
    const int s0 = g_off[g_rowexp[row * 2 + 0]] + g_rowpos[row * 2 + 0];
    const int s1 = g_off[g_rowexp[row * 2 + 1]] + g_rowpos[row * 2 + 1];
    const float* P0 = &g_P[(size_t)s0 * NC];
    const float* P1 = &g_P[(size_t)s1 * NC];
    for (int c = threadIdx.x; c < NC; c += 256) {
        float comb = P0[c] + P1[c];
        if (comb == 0.0f) comb = 2.2204460492503131e-16f;
        out[(size_t)row * NC + c] = logf(comb);
    }
    if (row == 0 && threadIdx.x == 0 && out_size > NB * NC)
        out[NB * NC] = g_loss;
}

// ---------------- launch ----------------
extern "C" void kernel_launch(void* const* d_in, const int* in_sizes, int n_in,
                              void* d_out, int out_size)
{
    const float* x   = (const float*)d_in[0];
    const float* x2  = (const float*)d_in[1];
    const float* Wg1 = (const float*)d_in[2];
    const float* bg1 = (const float*)d_in[3];
    const float* Wg2 = (const float*)d_in[4];
    const float* bg2 = (const float*)d_in[5];
    const float* W1  = (const float*)d_in[6];
    const float* b1  = (const float*)d_in[7];
    const float* W2  = (const float*)d_in[8];
    const float* b2  = (const float*)d_in[9];
    float* out = (float*)d_out;

    zero_counts<<<1, 32>>>();
    gemm0_split<<<dim3(NHG / 128, NB / 128), 256>>>(x, Wg1, bg1);
    gating_topk<<<NB / 8, 256>>>(Wg2, bg2);
    offsets_kernel<<<1, 32>>>();
    emma<1><<<dim3(NH / 128, NB / 128, NE), 256>>>(x2, W1, b1);
    emma<2><<<dim3(NC / 128, NB / 128, NE), 256>>>(nullptr, W2, b2);
    softmax_gate<<<dim3(NE, NB / 8), 256>>>();
    loss_kernel<<<1, 256>>>();
    finalize_kernel<<<NB, 256>>>(out, out_size);
}

// round 8
// speedup vs baseline: 4.8521x; 1.0620x over previous
#include <cuda_runtime.h>
#include <cuda_fp16.h>
#include <math.h>
#include <stdint.h>

// ---------------- problem constants ----------------
#define NB    4096
#define NDG   1024
#define NDI   1024
#define NHG   512
#define NE    8
#define NH    2048
#define NC    512
#define TEMPR 5.0f
#define NASSIGN (NB*2)

// ---------------- scratch ----------------
__device__ float g_hg[NB * NHG];
__device__ float g_gates[NB * NE];
__device__ int   g_cnt[NE];
__device__ int   g_off[NE];
__device__ int   g_rowlist[NE * NB];
__device__ float g_gatelist[NE * NB];
__device__ int   g_rowexp[NB * 2];
__device__ int   g_rowpos[NB * 2];
__device__ __half g_He[(size_t)NASSIGN * NH];
__device__ float g_P[(size_t)NASSIGN * NC];
__device__ float g_loss;

__global__ void zero_counts() {
    if (threadIdx.x < NE) g_cnt[threadIdx.x] = 0;
}
__global__ void offsets_kernel() {
    if (threadIdx.x == 0) {
        int o = 0;
        for (int e = 0; e < NE; e++) { g_off[e] = o; o += g_cnt[e]; }
    }
}

// ---------------- helpers ----------------
__device__ __forceinline__ uint32_t smem_u32(const void* p) {
    uint32_t a;
    asm("{ .reg .u64 t; cvta.to.shared.u64 t, %1; cvt.u32.u64 %0, t; }" : "=r"(a) : "l"(p));
    return a;
}
__device__ __forceinline__ uint32_t packh(float a, float b) {
    __half2 h = __floats2half2_rn(a, b);
    return *reinterpret_cast<uint32_t*>(&h);
}
__device__ __forceinline__ void mma_fp16(float* d, const uint32_t* a,
                                         const uint32_t* b, const float* c) {
    asm volatile(
        "mma.sync.aligned.m16n8k16.row.col.f32.f16.f16.f32 "
        "{%0,%1,%2,%3}, {%4,%5,%6,%7}, {%8,%9}, {%10,%11,%12,%13};\n"
        : "=f"(d[0]), "=f"(d[1]), "=f"(d[2]), "=f"(d[3])
        : "r"(a[0]), "r"(a[1]), "r"(a[2]), "r"(a[3]),
          "r"(b[0]), "r"(b[1]),
          "f"(c[0]), "f"(c[1]), "f"(c[2]), "f"(c[3]));
}
__device__ __forceinline__ void ldsm_x4(uint32_t* d, uint32_t saddr) {
    asm volatile("ldmatrix.sync.aligned.m8n8.x4.shared.b16 {%0,%1,%2,%3}, [%4];"
        : "=r"(d[0]), "=r"(d[1]), "=r"(d[2]), "=r"(d[3]) : "r"(saddr));
}

// ============================================================================
// Expert GEMMs, fp16 tensor cores (R7 skeleton + A-side ldmatrix).
// MODE 1: He = relu(gather(x2) @ W1[e] + b1[e])   M=cnt_e N=2048 K=1024
// MODE 2: P  = He @ W2[e] + b2[e]                 M=cnt_e N=512  K=2048
// SMEM: A as u32 k-pairs [m][kp] pad 20; B as u32 k-pair-interleaved [kp][n] pad 136.
// ============================================================================
template<int MODE>
__global__ __launch_bounds__(256, 2)
void emma(const float* __restrict__ Af,
          const float* __restrict__ Wall,
          const float* __restrict__ biasAll)
{
    constexpr int BM = 128, BK = 32;
    constexpr int LDA = 20, LDB = 136;

    const int e = blockIdx.z;
    const int M = g_cnt[e];
    const int m0 = blockIdx.y * BM;
    if (m0 >= M) return;
    const int n0 = blockIdx.x * 128;

    constexpr int Kd  = (MODE == 1) ? NDI : NH;
    constexpr int ldw = (MODE == 1) ? NH  : NC;
    const float* W    = Wall + (size_t)e * Kd * ldw;
    const float* bias = biasAll + e * ldw;
    const int* rowlist = g_rowlist + e * NB;
    const size_t offE = (size_t)g_off[e];
    const __half* Ab = g_He + offE * NH;   // MODE 2 input

    __shared__ uint32_t As[2][BM][LDA];
    __shared__ uint32_t Bs[2][16][LDB];

    const int tid = threadIdx.x;
    // A gmem plan: 2 chunks of 8 k-values
    int arow[2], akc[2];
    size_t aoff[2];
#pragma unroll
    for (int c = 0; c < 2; c++) {
        int q = tid + 256 * c;
        arow[c] = q >> 2;
        akc[c]  = (q & 3) * 8;
        int gm = m0 + arow[c];
        if (MODE == 1) {
            int r = (gm < M) ? rowlist[gm] : rowlist[0];
            aoff[c] = (size_t)r * NDI;
        } else {
            int r = (gm < M) ? gm : 0;
            aoff[c] = (size_t)r * NH;
        }
    }
    // B gmem plan: 2 chunks of (2 k rows x 4 n)
    int bkp[2], bnq[2];
#pragma unroll
    for (int c = 0; c < 2; c++) {
        int q = tid + 256 * c;
        bkp[c] = q >> 5;
        bnq[c] = (q & 31) * 4;
    }

    const int warp = tid >> 5;
    const int wm = warp >> 1, wn = warp & 1;
    const int lane = tid & 31;
    const int g = lane >> 2, tg = lane & 3;

    // ldmatrix lane address components (verified conflict-free with LDA=20)
    const uint32_t asbase = smem_u32(&As[0][0][0]);
    const int lrow = lane & 15;
    const int lcol = (lane >> 2) & 4;

    float acc[2][8][4];
#pragma unroll
    for (int i = 0; i < 2; i++)
#pragma unroll
        for (int j = 0; j < 8; j++)
#pragma unroll
            for (int q = 0; q < 4; q++) acc[i][j][q] = 0.0f;

    float4 ra[2][2];
    uint4  rab[2];
    float4 rb[2][2];

    auto LDGt = [&](int k0) {
#pragma unroll
        for (int c = 0; c < 2; c++) {
            if (MODE == 1) {
                ra[c][0] = *(const float4*)(Af + aoff[c] + k0 + akc[c]);
                ra[c][1] = *(const float4*)(Af + aoff[c] + k0 + akc[c] + 4);
            } else {
                rab[c] = *(const uint4*)(Ab + aoff[c] + k0 + akc[c]);
            }
        }
#pragma unroll
        for (int c = 0; c < 2; c++) {
            rb[c][0] = *(const float4*)(W + (size_t)(k0 + 2 * bkp[c]) * ldw + n0 + bnq[c]);
            rb[c][1] = *(const float4*)(W + (size_t)(k0 + 2 * bkp[c] + 1) * ldw + n0 + bnq[c]);
        }
    };
    auto STSt = [&](int s) {
#pragma unroll
        for (int c = 0; c < 2; c++) {
            if (MODE == 1) {
                uint4 u;
                u.x = packh(ra[c][0].x, ra[c][0].y);
                u.y = packh(ra[c][0].z, ra[c][0].w);
                u.z = packh(ra[c][1].x, ra[c][1].y);
                u.w = packh(ra[c][1].z, ra[c][1].w);
                *(uint4*)&As[s][arow[c]][akc[c] >> 1] = u;
            } else {
                *(uint4*)&As[s][arow[c]][akc[c] >> 1] = rab[c];
            }
        }
#pragma unroll
        for (int c = 0; c < 2; c++) {
            uint4 u;
            u.x = packh(rb[c][0].x, rb[c][1].x);
            u.y = packh(rb[c][0].y, rb[c][1].y);
            u.z = packh(rb[c][0].z, rb[c][1].z);
            u.w = packh(rb[c][0].w, rb[c][1].w);
            *(uint4*)&Bs[s][bkp[c]][bnq[c]] = u;
        }
    };

    LDGt(0);
    STSt(0);
    __syncthreads();

    const int T = Kd / BK;
    for (int t = 0; t < T; t++) {
        const int s = t & 1;
        if (t + 1 < T) LDGt((t + 1) * BK);

#pragma unroll
        for (int ksub = 0; ksub < 2; ksub++) {
            const int kb = ksub * 8;
            uint32_t af[2][4];
#pragma unroll
            for (int mt = 0; mt < 2; mt++) {
                const int mr = wm * 32 + mt * 16;
                const uint32_t addr = asbase +
                    ((uint32_t)(s * BM * LDA + (mr + lrow) * LDA + kb + lcol)) * 4u;
                ldsm_x4(af[mt], addr);
            }
#pragma unroll
            for (int nt = 0; nt < 8; nt++) {
                const int nc = wn * 64 + nt * 8 + g;
                uint32_t bf[2];
                bf[0] = Bs[s][kb + tg    ][nc];
                bf[1] = Bs[s][kb + tg + 4][nc];
#pragma unroll
                for (int mt = 0; mt < 2; mt++)
                    mma_fp16(acc[mt][nt], af[mt], bf, acc[mt][nt]);
            }
        }

        if (t + 1 < T) {
            STSt((t + 1) & 1);
            __syncthreads();
        }
    }

    // epilogue
    __half* Ch = g_He + offE * NH;   // MODE 1 out
    float*  Cf = g_P  + offE * NC;   // MODE 2 out
#pragma unroll
    for (int mt = 0; mt < 2; mt++) {
        const int gm1 = m0 + wm * 32 + mt * 16 + g;
        const int gm2 = gm1 + 8;
#pragma unroll
        for (int nt = 0; nt < 8; nt++) {
            const int col = n0 + wn * 64 + nt * 8 + tg * 2;
            const float b0 = bias[col], b1 = bias[col + 1];
            if (MODE == 1) {
                if (gm1 < M) {
                    float v0 = fmaxf(acc[mt][nt][0] + b0, 0.f);
                    float v1 = fmaxf(acc[mt][nt][1] + b1, 0.f);
                    *(uint32_t*)(Ch + (size_t)gm1 * NH + col) = packh(v0, v1);
                }
                if (gm2 < M) {
                    float v0 = fmaxf(acc[mt][nt][2] + b0, 0.f);
                    float v1 = fmaxf(acc[mt][nt][3] + b1, 0.f);
                    *(uint32_t*)(Ch + (size_t)gm2 * NH + col) = packh(v0, v1);
                }
            } else {
                if (gm1 < M)
                    *(float2*)(Cf + (size_t)gm1 * NC + col) =
                        make_float2(acc[mt][nt][0] + b0, acc[mt][nt][1] + b1);
                if (gm2 < M)
                    *(float2*)(Cf + (size_t)gm2 * NC + col) =
                        make_float2(acc[mt][nt][2] + b0, acc[mt][nt][3] + b1);
            }
        }
    }
}

// ============================================================================
// Gating layer 1: compensated fp16-split (hi*hi + hi*lo + lo*hi; err ~2^-22).
// Same structure as the passing bf16-split, dtype only.
// g_hg = relu(x @ Wg1 + bg1)   M=4096 N=512 K=1024
// ============================================================================
__global__ __launch_bounds__(256, 2)
void gemm0_split(const float* __restrict__ A,
                 const float* __restrict__ W,
                 const float* __restrict__ bias)
{
    constexpr int BM = 128, BK = 32;
    constexpr int LDA = 20, LDB = 136;
    constexpr int ldw = NHG;

    const int m0 = blockIdx.y * BM;
    const int n0 = blockIdx.x * 128;

    __shared__ uint32_t AsH[BM][LDA];
    __shared__ uint32_t AsL[BM][LDA];
    __shared__ uint32_t BsH[16][LDB];
    __shared__ uint32_t BsL[16][LDB];

    const int tid = threadIdx.x;
    int arow[2], akc[2];
    size_t aoff[2];
#pragma unroll
    for (int c = 0; c < 2; c++) {
        int q = tid + 256 * c;
        arow[c] = q >> 2;
        akc[c]  = (q & 3) * 8;
        aoff[c] = (size_t)(m0 + arow[c]) * NDG;
    }
    int bkp[2], bnq[2];
#pragma unroll
    for (int c = 0; c < 2; c++) {
        int q = tid + 256 * c;
        bkp[c] = q >> 5;
        bnq[c] = (q & 31) * 4;
    }

    const int warp = tid >> 5;
    const int wm = warp >> 1, wn = warp & 1;
    const int lane = tid & 31;
    const int g = lane >> 2, tg = lane & 3;

    float acc[2][8][4];
#pragma unroll
    for (int i = 0; i < 2; i++)
#pragma unroll
        for (int j = 0; j < 8; j++)
#pragma unroll
            for (int q = 0; q < 4; q++) acc[i][j][q] = 0.0f;

    auto splitpack = [](float a, float b, uint32_t& uh, uint32_t& ul) {
        __half ha = __float2half_rn(a);
        __half hb = __float2half_rn(b);
        float la = a - __half2float(ha);
        float lb = b - __half2float(hb);
        __half2 h2; h2.x = ha; h2.y = hb;
        uh = *reinterpret_cast<uint32_t*>(&h2);
        ul = packh(la, lb);
    };

    const int T = NDG / BK;
    for (int t = 0; t < T; t++) {
        const int k0 = t * BK;
        float4 ra[2][2], rb[2][2];
#pragma unroll
        for (int c = 0; c < 2; c++) {
            ra[c][0] = *(const float4*)(A + aoff[c] + k0 + akc[c]);
            ra[c][1] = *(const float4*)(A + aoff[c] + k0 + akc[c] + 4);
            rb[c][0] = *(const float4*)(W + (size_t)(k0 + 2 * bkp[c]) * ldw + n0 + bnq[c]);
            rb[c][1] = *(const float4*)(W + (size_t)(k0 + 2 * bkp[c] + 1) * ldw + n0 + bnq[c]);
        }
        __syncthreads();
#pragma unroll
        for (int c = 0; c < 2; c++) {
            uint4 uh, ul;
            splitpack(ra[c][0].x, ra[c][0].y, uh.x, ul.x);
            splitpack(ra[c][0].z, ra[c][0].w, uh.y, ul.y);
            splitpack(ra[c][1].x, ra[c][1].y, uh.z, ul.z);
            splitpack(ra[c][1].z, ra[c][1].w, uh.w, ul.w);
            *(uint4*)&AsH[arow[c]][akc[c] >> 1] = uh;
            *(uint4*)&AsL[arow[c]][akc[c] >> 1] = ul;
        }
#pragma unroll
        for (int c = 0; c < 2; c++) {
            uint4 uh, ul;
            splitpack(rb[c][0].x, rb[c][1].x, uh.x, ul.x);
            splitpack(rb[c][0].y, rb[c][1].y, uh.y, ul.y);
            splitpack(rb[c][0].z, rb[c][1].z, uh.z, ul.z);
            splitpack(rb[c][0].w, rb[c][1].w, uh.w, ul.w);
            *(uint4*)&BsH[bkp[c]][bnq[c]] = uh;
            *(uint4*)&BsL[bkp[c]][bnq[c]] = ul;
        }
        __syncthreads();

#pragma unroll
        for (int ksub = 0; ksub < 2; ksub++) {
            const int kb = ksub * 8;
            uint32_t afh[2][4], afl[2][4];
#pragma unroll
            for (int mt = 0; mt < 2; mt++) {
                const int mr = wm * 32 + mt * 16;
                afh[mt][0] = AsH[mr + g    ][kb + tg];
                afh[mt][1] = AsH[mr + g + 8][kb + tg];
                afh[mt][2] = AsH[mr + g    ][kb + tg + 4];
                afh[mt][3] = AsH[mr + g + 8][kb + tg + 4];
                afl[mt][0] = AsL[mr + g    ][kb + tg];
                afl[mt][1] = AsL[mr + g + 8][kb + tg];
                afl[mt][2] = AsL[mr + g    ][kb + tg + 4];
                afl[mt][3] = AsL[mr + g + 8][kb + tg + 4];
            }
#pragma unroll
            for (int nt = 0; nt < 8; nt++) {
                const int nc = wn * 64 + nt * 8 + g;
                uint32_t bfh[2], bfl[2];
                bfh[0] = BsH[kb + tg    ][nc];
                bfh[1] = BsH[kb + tg + 4][nc];
                bfl[0] = BsL[kb + tg    ][nc];
                bfl[1] = BsL[kb + tg + 4][nc];
#pragma unroll
                for (int mt = 0; mt < 2; mt++) {
                    mma_fp16(acc[mt][nt], afh[mt], bfh, acc[mt][nt]);
                    mma_fp16(acc[mt][nt], afh[mt], bfl, acc[mt][nt]);
                    mma_fp16(acc[mt][nt], afl[mt], bfh, acc[mt][nt]);
                }
            }
        }
    }

#pragma unroll
    for (int mt = 0; mt < 2; mt++) {
        const int gm1 = m0 + wm * 32 + mt * 16 + g;
        const int gm2 = gm1 + 8;
#pragma unroll
        for (int nt = 0; nt < 8; nt++) {
            const int col = n0 + wn * 64 + nt * 8 + tg * 2;
            const float b0 = bias[col], b1 = bias[col + 1];
            *(float2*)(g_hg + (size_t)gm1 * NHG + col) =
                make_float2(fmaxf(acc[mt][nt][0] + b0, 0.f), fmaxf(acc[mt][nt][1] + b1, 0.f));
            *(float2*)(g_hg + (size_t)gm2 * NHG + col) =
                make_float2(fmaxf(acc[mt][nt][2] + b0, 0.f), fmaxf(acc[mt][nt][3] + b1, 0.f));
        }
    }
}

// ---------------- gating layer 2 + top-2 + dispatch ----------------
__global__ __launch_bounds__(256)
void gating_topk(const float* __restrict__ Wg2, const float* __restrict__ bg2)
{
    __shared__ float sW[NE][NHG];
    __shared__ float sb[NE];
    const int tid = threadIdx.x;
    for (int i = tid; i < NE * NHG; i += 256)
        sW[i >> 9][i & (NHG - 1)] = Wg2[(i & (NHG - 1)) * NE + (i >> 9)];
    if (tid < NE) sb[tid] = bg2[tid];
    __syncthreads();

    const int warp = tid >> 5, lane = tid & 31;
    const int row = blockIdx.x * 8 + warp;

    float acc[NE];
#pragma unroll
    for (int j = 0; j < NE; j++) acc[j] = 0.0f;
    const float* hr = &g_hg[(size_t)row * NHG];
#pragma unroll 4
    for (int t = 0; t < NHG / 32; t++) {
        float v = hr[t * 32 + lane];
#pragma unroll
        for (int j = 0; j < NE; j++) acc[j] = fmaf(v, sW[j][t * 32 + lane], acc[j]);
    }
#pragma unroll
    for (int j = 0; j < NE; j++)
#pragma unroll
        for (int o = 16; o > 0; o >>= 1)
            acc[j] += __shfl_xor_sync(0xffffffffu, acc[j], o);

    if (lane == 0) {
        float lg[NE];
#pragma unroll
        for (int j = 0; j < NE; j++) lg[j] = acc[j] + sb[j];
        int b0 = 0; float v0 = lg[0];
#pragma unroll
        for (int j = 1; j < NE; j++) if (lg[j] > v0) { v0 = lg[j]; b0 = j; }
        int b1 = -1; float v1 = -INFINITY;
#pragma unroll
        for (int j = 0; j < NE; j++) if (j != b0 && lg[j] > v1) { v1 = lg[j]; b1 = j; }

        float e1 = expf((v1 - v0) / TEMPR);
        float s = 1.0f + e1;
        float gg0 = 1.0f / s, gg1 = e1 / s;
#pragma unroll
        for (int j = 0; j < NE; j++) g_gates[row * NE + j] = 0.0f;
        g_gates[row * NE + b0] = gg0;
        g_gates[row * NE + b1] = gg1;

        int p0 = atomicAdd(&g_cnt[b0], 1);
        g_rowlist[b0 * NB + p0] = row;
        g_gatelist[b0 * NB + p0] = gg0;
        g_rowexp[row * 2 + 0] = b0;
        g_rowpos[row * 2 + 0] = p0;
        int p1 = atomicAdd(&g_cnt[b1], 1);
        g_rowlist[b1 * NB + p1] = row;
        g_gatelist[b1 * NB + p1] = gg1;
        g_rowexp[row * 2 + 1] = b1;
        g_rowpos[row * 2 + 1] = p1;
    }
}

// ---------------- row softmax * gate ----------------
__global__ __launch_bounds__(256)
void softmax_gate()
{
    const int e = blockIdx.x;
    const int warp = threadIdx.x >> 5, lane = threadIdx.x & 31;
    const int i = blockIdx.y * 8 + warp;
    if (i >= g_cnt[e]) return;
    float* P = &g_P[(size_t)(g_off[e] + i) * NC];

    float v[NC / 32];
    float mx = -INFINITY;
#pragma unroll
    for (int t = 0; t < NC / 32; t++) { v[t] = P[t * 32 + lane]; mx = fmaxf(mx, v[t]); }
#pragma unroll
    for (int o = 16; o > 0; o >>= 1) mx = fmaxf(mx, __shfl_xor_sync(0xffffffffu, mx, o));
    float sum = 0.0f;
#pragma unroll
    for (int t = 0; t < NC / 32; t++) { v[t] = expf(v[t] - mx); sum += v[t]; }
#pragma unroll
    for (int o = 16; o > 0; o >>= 1) sum += __shfl_xor_sync(0xffffffffu, sum, o);
    const float inv = g_gatelist[e * NB + i] / sum;
#pragma unroll
    for (int t = 0; t < NC / 32; t++) P[t * 32 + lane] = v[t] * inv;
}

// ---------------- load-balance loss ----------------
__global__ __launch_bounds__(256)
void loss_kernel()
{
    const int e = threadIdx.x >> 5, lane = threadIdx.x & 31;
    float s = 0.0f;
    for (int r = lane; r < NB; r += 32) s += g_gates[r * NE + e];
#pragma unroll
    for (int o = 16; o > 0; o >>= 1) s += __shfl_xor_sync(0xffffffffu, s, o);
    __shared__ float imp[NE];
    if (lane == 0) imp[e] = s;
    __syncthreads();
    if (threadIdx.x == 0) {
        double mi = 0.0, ml = 0.0;
        for (int j = 0; j < NE; j++) { mi += (double)imp[j]; ml += (double)g_cnt[j]; }
        mi /= NE; ml /= NE;
        double vi = 0.0, vl = 0.0;
        for (int j = 0; j < NE; j++) {
            double di = (double)imp[j] - mi;  vi += di * di;
            double dl = (double)g_cnt[j] - ml; vl += dl * dl;
        }
        vi /= (NE - 1); vl /= (NE - 1);
        g_loss = (float)((vi / (mi * mi + 1e-10) + vl / (ml * ml + 1e-10)) * 0.01);
    }
}

// ---------------- combine + log ----------------
__global__ __launch_bounds__(256)
void finalize_kernel(float* __restrict__ out, int out_size)
{
    const int row = blockIdx.x;
    const int s0 = g_off[g_rowexp[row * 2 + 0]] + g_rowpos[row * 2 + 0];
    const int s1 = g_off[g_rowexp[row * 2 + 1]] + g_rowpos[row * 2 + 1];
    const float* P0 = &g_P[(size_t)s0 * NC];
    const float* P1 = &g_P[(size_t)s1 * NC];
    for (int c = threadIdx.x; c < NC; c += 256) {
        float comb = P0[c] + P1[c];
        if (comb == 0.0f) comb = 2.2204460492503131e-16f;
        out[(size_t)row * NC + c] = logf(comb);
    }
    if (row == 0 && threadIdx.x == 0 && out_size > NB * NC)
        out[NB * NC] = g_loss;
}

// ---------------- launch ----------------
extern "C" void kernel_launch(void* const* d_in, const int* in_sizes, int n_in,
                              void* d_out, int out_size)
{
    const float* x   = (const float*)d_in[0];
    const float* x2  = (const float*)d_in[1];
    const float* Wg1 = (const float*)d_in[2];
    const float* bg1 = (const float*)d_in[3];
    const float* Wg2 = (const float*)d_in[4];
    const float* bg2 = (const float*)d_in[5];
    const float* W1  = (const float*)d_in[6];
    const float* b1  = (const float*)d_in[7];
    const float* W2  = (const float*)d_in[8];
    const float* b2  = (const float*)d_in[9];
    float* out = (float*)d_out;

    zero_counts<<<1, 32>>>();
    gemm0_split<<<dim3(NHG / 128, NB / 128), 256>>>(x, Wg1, bg1);
    gating_topk<<<NB / 8, 256>>>(Wg2, bg2);
    offsets_kernel<<<1, 32>>>();
    emma<1><<<dim3(NH / 128, NB / 128, NE), 256>>>(x2, W1, b1);
    emma<2><<<dim3(NC / 128, NB / 128, NE), 256>>>(nullptr, W2, b2);
    softmax_gate<<<dim3(NE, NB / 8), 256>>>();
    loss_kernel<<<1, 256>>>();
    finalize_kernel<<<NB, 256>>>(out, out_size);
}